// round 15
// baseline (speedup 1.0000x reference)
#include <cuda_runtime.h>
#include <cuda_fp16.h>
#include <cstdint>

#define VOCABN 32000
#define EMBEDN 256
#define H1N    512
#define KVN    128
#define BN_    32
#define SN     512
#define TN     256
#define MROWS  (BN_*TN)   // 8192

// ---------------- scratch (static device globals; no allocation) ----------------
__device__ float  g_gates1[MROWS * 3 * H1N];
__device__ float  g_gates2[MROWS * 3 * KVN];
__device__ __half g_Eh  [VOCABN * EMBEDN];
__device__ __half g_W1h [3 * H1N * EMBEDN];
__device__ __half g_W2h [3 * KVN * H1N];
__device__ __half g_keyh[BN_ * SN * KVN];
__device__ __half g_valueh[BN_ * SN * KVN];
__device__ __half g_h1h [MROWS * H1N];
__device__ __half g_outctxh[MROWS * EMBEDN];

// ---------------- helpers ----------------
__device__ __forceinline__ void cp16(void* dst_smem, const void* src) {
    unsigned s = (unsigned)__cvta_generic_to_shared(dst_smem);
    asm volatile("cp.async.cg.shared.global [%0], [%1], 16;" :: "r"(s), "l"(src));
}
__device__ __forceinline__ float sigf(float x) { return 1.f / (1.f + expf(-x)); }

// ---------------- one-shot fp32->fp16 conversion for ALL operands ----------------
__global__ void conv_all(const float4* __restrict__ E,  const float4* __restrict__ W1,
                         const float4* __restrict__ W2, const float4* __restrict__ key,
                         const float4* __restrict__ value,
                         uint2* __restrict__ Eh,  uint2* __restrict__ W1h,
                         uint2* __restrict__ W2h, uint2* __restrict__ keyh,
                         uint2* __restrict__ valueh)
{
    const long nE   = (long)VOCABN * EMBEDN / 4;
    const long nW1g = H1N * EMBEDN / 4;
    const long nW2g = KVN * H1N / 4;
    const long nKey = (long)BN_ * SN * KVN / 4;

    long o = (long)blockIdx.x * blockDim.x + threadIdx.x;
    const float4* src; uint2* dst; long si, di;
    if (o < nE) { src = E; dst = Eh; si = o; di = o; }
    else {
        o -= nE;
        if (o < 3 * nW1g) {
            long gate = o >> 15, r = o & (nW1g - 1);
            long sg = (gate == 0) ? 0 : gate + 1;
            src = W1; dst = W1h; si = sg * nW1g + r; di = o;
        } else {
            o -= 3 * nW1g;
            if (o < 3 * nW2g) {
                long gate = o >> 14, r = o & (nW2g - 1);
                long sg = (gate == 0) ? 0 : gate + 1;
                src = W2; dst = W2h; si = sg * nW2g + r; di = o;
            } else {
                o -= 3 * nW2g;
                if (o < nKey) { src = key; dst = keyh; si = o; di = o; }
                else {
                    o -= nKey;
                    if (o >= nKey) return;
                    src = value; dst = valueh; si = o; di = o;
                }
            }
        }
    }
    float4 v = src[si];
    __half2 h0 = __floats2half2_rn(v.x, v.y);
    __half2 h1 = __floats2half2_rn(v.z, v.w);
    uint2 out;
    out.x = *reinterpret_cast<unsigned*>(&h0);
    out.y = *reinterpret_cast<unsigned*>(&h1);
    dst[di] = out;
}
#define CONV_TOTAL (2048000 + 3*32768 + 3*16384 + 524288 + 524288)

// =================================================================================
// PERSISTENT-A logits GEMM v4: M-tile 256 (halves B L2 re-reads vs v3).
// 256 threads, 8 warps (4m x 2n), warp tile 64x64, 1 CTA/SM (8 warps/SM kept).
// A 256x256 resident XOR-swizzled (131 KB); 3-slot B ring; single sync/chunk;
// .cs streaming stores.
// =================================================================================
#define PA_NT  8
#define A_STR  256
#define A_ROWS 256
#define A_SMH  (A_ROWS * A_STR)            // 65536 halves = 131072 B
#define B_STR  64
#define B_SLOT (128 * B_STR)               // 8192 halves = 16384 B
#define PA_SMEM ((A_SMH + 3 * B_SLOT) * 2) // 180224 B

__global__ void __launch_bounds__(256, 1)
logits_pa(const __half* __restrict__ Eh, const __half* __restrict__ Bm,
          const float* __restrict__ bias, float* __restrict__ out)
{
    extern __shared__ __half sh[];
    __half* Ash = sh;
    __half* Bsh = sh + A_SMH;

    const int tid  = threadIdx.x;
    const int warp = tid >> 5, lane = tid & 31;
    const int wm = warp >> 1, wn = warp & 1;     // 4m x 2n
    const int g  = lane >> 2, tq = lane & 3;
    const int quad = lane >> 3, lr = lane & 7;
    const int bm0 = blockIdx.y * 256;
    const int nt0 = blockIdx.x * PA_NT;

    // resident A: 256 rows x 32 segs = 8192 chunks, 32 per thread
#pragma unroll
    for (int i = 0; i < 32; i++) {
        int c = tid + i * 256;
        int r = c >> 5, seg = c & 31;
        int segw = (seg & ~7) | ((seg & 7) ^ (r & 7));
        cp16(&Ash[r * A_STR + segw * 8], Eh + (long)(bm0 + r) * EMBEDN + seg * 8);
    }
    asm volatile("cp.async.commit_group;" ::: "memory");

    // B chunk mapping: 1024 chunks, 4 per thread
    int rB[4], sB[4], swB[4];
#pragma unroll
    for (int i = 0; i < 4; i++) {
        int c = tid + i * 256;
        rB[i] = c >> 3; sB[i] = c & 7;
        swB[i] = sB[i] ^ (rB[i] & 7);
    }
#pragma unroll
    for (int p = 0; p < 2; p++) {
        const __half* src = Bm + (long)(nt0 * 128) * EMBEDN + p * 64;
#pragma unroll
        for (int i = 0; i < 4; i++)
            cp16(&Bsh[p * B_SLOT + rB[i] * B_STR + swB[i] * 8],
                 src + (long)rB[i] * EMBEDN + sB[i] * 8);
        asm volatile("cp.async.commit_group;" ::: "memory");
    }

    float bb[8];
#pragma unroll
    for (int mi = 0; mi < 4; mi++)
#pragma unroll
        for (int rr = 0; rr < 2; rr++)
            bb[mi * 2 + rr] = bias[bm0 + wm * 64 + mi * 16 + g + rr * 8];

    float acc[4][8][4];
#pragma unroll
    for (int i = 0; i < 4; i++)
#pragma unroll
        for (int j = 0; j < 8; j++)
#pragma unroll
            for (int q = 0; q < 4; q++) acc[i][j][q] = 0.f;

    const int NCH = PA_NT * 4;
    int slot = 0;
    for (int gch = 0; gch < NCH; gch++) {
        if (gch == NCH - 1) {
            asm volatile("cp.async.wait_group 0;" ::: "memory");
        } else {
            asm volatile("cp.async.wait_group 1;" ::: "memory");
        }
        __syncthreads();   // single sync per chunk

        if (gch + 2 < NCH) {
            int g2 = gch + 2;
            int nt = g2 >> 2, kc = g2 & 3;
            int s2 = g2 % 3;
            const __half* src = Bm + (long)((nt0 + nt) * 128) * EMBEDN + kc * 64;
#pragma unroll
            for (int i = 0; i < 4; i++)
                cp16(&Bsh[s2 * B_SLOT + rB[i] * B_STR + swB[i] * 8],
                     src + (long)rB[i] * EMBEDN + sB[i] * 8);
            asm volatile("cp.async.commit_group;" ::: "memory");
        }

        const __half* Bslot = Bsh + slot * B_SLOT;
        const int kbase = (gch & 3) * 64;

#pragma unroll
        for (int kk = 0; kk < 64; kk += 16) {
            unsigned af[4][4], bf[8][2];
#pragma unroll
            for (int mi = 0; mi < 4; mi++) {
                int row = wm * 64 + mi * 16 + lr + (quad & 1) * 8;
                int seg = ((kbase + kk) >> 3) + (quad >> 1);
                int segw = (seg & ~7) | ((seg & 7) ^ (row & 7));
                unsigned addr = (unsigned)__cvta_generic_to_shared(
                    &Ash[row * A_STR + segw * 8]);
                asm volatile(
                    "ldmatrix.sync.aligned.m8n8.x4.shared.b16 {%0,%1,%2,%3}, [%4];"
                    : "=r"(af[mi][0]), "=r"(af[mi][1]),
                      "=r"(af[mi][2]), "=r"(af[mi][3]) : "r"(addr));
            }
#pragma unroll
            for (int np = 0; np < 4; np++) {
                int row = wn * 64 + np * 16 + lr + (quad & 1) * 8;
                int seg = (kk >> 3) + (quad >> 1);
                int segw = seg ^ (row & 7);
                unsigned addr = (unsigned)__cvta_generic_to_shared(
                    &Bslot[row * B_STR + segw * 8]);
                unsigned r0, r1, r2, r3;
                asm volatile(
                    "ldmatrix.sync.aligned.m8n8.x4.shared.b16 {%0,%1,%2,%3}, [%4];"
                    : "=r"(r0), "=r"(r1), "=r"(r2), "=r"(r3) : "r"(addr));
                bf[2 * np + 0][0] = r0; bf[2 * np + 0][1] = r2;
                bf[2 * np + 1][0] = r1; bf[2 * np + 1][1] = r3;
            }
#pragma unroll
            for (int mi = 0; mi < 4; mi++)
#pragma unroll
                for (int ni = 0; ni < 8; ni++)
                    asm volatile(
                        "mma.sync.aligned.m16n8k16.row.col.f32.f16.f16.f32 "
                        "{%0,%1,%2,%3}, {%4,%5,%6,%7}, {%8,%9}, {%0,%1,%2,%3};\n"
                        : "+f"(acc[mi][ni][0]), "+f"(acc[mi][ni][1]),
                          "+f"(acc[mi][ni][2]), "+f"(acc[mi][ni][3])
                        : "r"(af[mi][0]), "r"(af[mi][1]),
                          "r"(af[mi][2]), "r"(af[mi][3]),
                          "r"(bf[ni][0]), "r"(bf[ni][1]));
        }
        slot = (slot + 1 == 3) ? 0 : slot + 1;

        if ((gch & 3) == 3) {
            int ncol0 = (nt0 + (gch >> 2)) * 128;
#pragma unroll
            for (int mi = 0; mi < 4; mi++) {
#pragma unroll
                for (int ni = 0; ni < 8; ni++) {
                    int row = bm0 + wm * 64 + mi * 16 + g;
                    int col = ncol0 + wn * 64 + ni * 8 + 2 * tq;
                    int bidx = col >> 8;
                    int t    = col & 255;
#pragma unroll
                    for (int rr = 0; rr < 2; rr++) {
                        int r = row + rr * 8;
                        float v0 = acc[mi][ni][rr * 2 + 0] + bb[mi * 2 + rr];
                        float v1 = acc[mi][ni][rr * 2 + 1] + bb[mi * 2 + rr];
                        __stcs(reinterpret_cast<float2*>(
                                   out + (long)bidx * VOCABN * TN + (long)r * TN + t),
                               make_float2(v0, v1));
                        acc[mi][ni][rr * 2 + 0] = 0.f;
                        acc[mi][ni][rr * 2 + 1] = 0.f;
                    }
                }
            }
        }
    }
}

// =================================================================================
// fp16 TN GEMM, CTA 128x128, BK=64, 3-stage cp.async (verified R7/R8/R13)
// MODE 0: plain | MODE 1: token-gather A
// =================================================================================
#define GBM 128
#define GBN 128
#define GBK 64
#define LDH 72
#define TSTG (128 * LDH)
#define STGH (2 * TSTG)
#define GSMEM (3 * STGH * 2)

template <int MODE>
__global__ void __launch_bounds__(256, 2)
gemm_h(const __half* __restrict__ A, const __half* __restrict__ Bmat,
       float* __restrict__ C,
       int K, int lda, int ldb, int ldc,
       const int* __restrict__ ytok)
{
    extern __shared__ __half sh[];

    const int tid  = threadIdx.x;
    const int warp = tid >> 5, lane = tid & 31;
    const int wm = warp >> 2, wn = warp & 3;
    const int g  = lane >> 2, tq = lane & 3;
    const int quad = lane >> 3, lr = lane & 7;
    const int bm0 = blockIdx.y * GBM;
    const int bn0 = blockIdx.x * GBN;

    int rA[4], sA_[4];
    const __half* srcA[4];
    const __half* srcB[4];
#pragma unroll
    for (int i = 0; i < 4; i++) {
        int c   = tid + i * 256;
        int r   = c >> 3;
        int seg = c & 7;
        rA[i] = r; sA_[i] = seg;
        if (MODE == 1) {
            int m   = bm0 + r;
            int tok = ((m & (TN - 1)) == 0) ? 0 : ytok[m - 1];
            srcA[i] = A + (long)tok * lda + seg * 8;
        } else {
            srcA[i] = A + (long)(bm0 + r) * lda + seg * 8;
        }
        srcB[i] = Bmat + (long)(bn0 + r) * ldb + seg * 8;
    }

    float acc[4][4][4];
#pragma unroll
    for (int i = 0; i < 4; i++)
#pragma unroll
        for (int j = 0; j < 4; j++)
#pragma unroll
            for (int q = 0; q < 4; q++) acc[i][j][q] = 0.f;

    const int nt = K / GBK;

#pragma unroll
    for (int s = 0; s < 2; s++) {
        if (s < nt) {
            __half* Ad = sh + s * STGH;
            __half* Bd = Ad + TSTG;
            int k0 = s * GBK;
#pragma unroll
            for (int i = 0; i < 4; i++) {
                cp16(&Ad[rA[i] * LDH + sA_[i] * 8], srcA[i] + k0);
                cp16(&Bd[rA[i] * LDH + sA_[i] * 8], srcB[i] + k0);
            }
            asm volatile("cp.async.commit_group;" ::: "memory");
        }
    }

    int buf = 0;
    for (int kt = 0; kt < nt; kt++) {
        if (kt + 1 < nt) {
            asm volatile("cp.async.wait_group 1;" ::: "memory");
        } else {
            asm volatile("cp.async.wait_group 0;" ::: "memory");
        }
        __syncthreads();

        if (kt + 2 < nt) {
            int sb2 = (kt + 2) % 3;
            __half* Ad = sh + sb2 * STGH;
            __half* Bd = Ad + TSTG;
            int k0 = (kt + 2) * GBK;
#pragma unroll
            for (int i = 0; i < 4; i++) {
                cp16(&Ad[rA[i] * LDH + sA_[i] * 8], srcA[i] + k0);
                cp16(&Bd[rA[i] * LDH + sA_[i] * 8], srcB[i] + k0);
            }
            asm volatile("cp.async.commit_group;" ::: "memory");
        }

        const __half* Asb = sh + buf * STGH;
        const __half* Bsb = Asb + TSTG;

#pragma unroll
        for (int kk = 0; kk < GBK; kk += 16) {
            unsigned af[4][4], bf[4][2];
#pragma unroll
            for (int mi = 0; mi < 4; mi++) {
                int row = wm * 64 + mi * 16 + lr + (quad & 1) * 8;
                int col = kk + (quad >> 1) * 8;
                unsigned addr = (unsigned)__cvta_generic_to_shared(
                    &Asb[row * LDH + col]);
                asm volatile(
                    "ldmatrix.sync.aligned.m8n8.x4.shared.b16 {%0,%1,%2,%3}, [%4];"
                    : "=r"(af[mi][0]), "=r"(af[mi][1]),
                      "=r"(af[mi][2]), "=r"(af[mi][3]) : "r"(addr));
            }
#pragma unroll
            for (int np = 0; np < 2; np++) {
                int row = wn * 32 + np * 16 + lr + (quad & 1) * 8;
                int col = kk + (quad >> 1) * 8;
                unsigned addr = (unsigned)__cvta_generic_to_shared(
                    &Bsb[row * LDH + col]);
                unsigned r0, r1, r2, r3;
                asm volatile(
                    "ldmatrix.sync.aligned.m8n8.x4.shared.b16 {%0,%1,%2,%3}, [%4];"
                    : "=r"(r0), "=r"(r1), "=r"(r2), "=r"(r3) : "r"(addr));
                bf[2 * np + 0][0] = r0; bf[2 * np + 0][1] = r2;
                bf[2 * np + 1][0] = r1; bf[2 * np + 1][1] = r3;
            }
#pragma unroll
            for (int mi = 0; mi < 4; mi++)
#pragma unroll
                for (int ni = 0; ni < 4; ni++)
                    asm volatile(
                        "mma.sync.aligned.m16n8k16.row.col.f32.f16.f16.f32 "
                        "{%0,%1,%2,%3}, {%4,%5,%6,%7}, {%8,%9}, {%0,%1,%2,%3};\n"
                        : "+f"(acc[mi][ni][0]), "+f"(acc[mi][ni][1]),
                          "+f"(acc[mi][ni][2]), "+f"(acc[mi][ni][3])
                        : "r"(af[mi][0]), "r"(af[mi][1]),
                          "r"(af[mi][2]), "r"(af[mi][3]),
                          "r"(bf[ni][0]), "r"(bf[ni][1]));
        }
        buf = (buf + 1) % 3;
        __syncthreads();
    }

#pragma unroll
    for (int mi = 0; mi < 4; mi++) {
#pragma unroll
        for (int ni = 0; ni < 4; ni++) {
            int row = bm0 + wm * 64 + mi * 16 + g;
            int col = bn0 + wn * 32 + ni * 8 + 2 * tq;
#pragma unroll
            for (int rr = 0; rr < 2; rr++) {
                int r = row + rr * 8;
                *reinterpret_cast<float2*>(C + (long)r * ldc + col) =
                    make_float2(acc[mi][ni][rr * 2 + 0], acc[mi][ni][rr * 2 + 1]);
            }
        }
    }
}

// =================================================================================
// SMALL-M fp16 TN GEMM for gates2 (verified R12/R13): CTA 64x128, 128 threads.
// =================================================================================
#define S_ASTG (64 * LDH)
#define S_BSTG (128 * LDH)
#define S_STG  (S_ASTG + S_BSTG)
#define S_SMEM (3 * S_STG * 2)

__global__ void __launch_bounds__(128, 2)
gemm_s(const __half* __restrict__ A, const __half* __restrict__ Bmat,
       float* __restrict__ C, int K, int lda, int ldb, int ldc)
{
    extern __shared__ __half sh[];

    const int tid  = threadIdx.x;
    const int warp = tid >> 5, lane = tid & 31;
    const int wn = warp;
    const int g  = lane >> 2, tq = lane & 3;
    const int quad = lane >> 3, lr = lane & 7;
    const int bm0 = blockIdx.y * 64;
    const int bn0 = blockIdx.x * 128;

    int rA[4], sA_[4];
    const __half* srcA[4];
#pragma unroll
    for (int i = 0; i < 4; i++) {
        int c = tid + i * 128;
        rA[i] = c >> 3; sA_[i] = c & 7;
        srcA[i] = A + (long)(bm0 + rA[i]) * lda + sA_[i] * 8;
    }
    int rBs[8], sBs[8];
    const __half* srcB[8];
#pragma unroll
    for (int i = 0; i < 8; i++) {
        int c = tid + i * 128;
        rBs[i] = c >> 3; sBs[i] = c & 7;
        srcB[i] = Bmat + (long)(bn0 + rBs[i]) * ldb + sBs[i] * 8;
    }

    float acc[4][4][4];
#pragma unroll
    for (int i = 0; i < 4; i++)
#pragma unroll
        for (int j = 0; j < 4; j++)
#pragma unroll
            for (int q = 0; q < 4; q++) acc[i][j][q] = 0.f;

    const int nt = K / GBK;

#pragma unroll
    for (int s = 0; s < 2; s++) {
        __half* Ad = sh + s * S_STG;
        __half* Bd = Ad + S_ASTG;
        int k0 = s * GBK;
#pragma unroll
        for (int i = 0; i < 4; i++)
            cp16(&Ad[rA[i] * LDH + sA_[i] * 8], srcA[i] + k0);
#pragma unroll
        for (int i = 0; i < 8; i++)
            cp16(&Bd[rBs[i] * LDH + sBs[i] * 8], srcB[i] + k0);
        asm volatile("cp.async.commit_group;" ::: "memory");
    }

    int buf = 0;
    for (int kt = 0; kt < nt; kt++) {
        if (kt + 1 < nt) {
            asm volatile("cp.async.wait_group 1;" ::: "memory");
        } else {
            asm volatile("cp.async.wait_group 0;" ::: "memory");
        }
        __syncthreads();

        if (kt + 2 < nt) {
            int sb2 = (kt + 2) % 3;
            __half* Ad = sh + sb2 * S_STG;
            __half* Bd = Ad + S_ASTG;
            int k0 = (kt + 2) * GBK;
#pragma unroll
            for (int i = 0; i < 4; i++)
                cp16(&Ad[rA[i] * LDH + sA_[i] * 8], srcA[i] + k0);
#pragma unroll
            for (int i = 0; i < 8; i++)
                cp16(&Bd[rBs[i] * LDH + sBs[i] * 8], srcB[i] + k0);
            asm volatile("cp.async.commit_group;" ::: "memory");
        }

        const __half* Asb = sh + buf * S_STG;
        const __half* Bsb = Asb + S_ASTG;

#pragma unroll
        for (int kk = 0; kk < GBK; kk += 16) {
            unsigned af[4][4], bf[4][2];
#pragma unroll
            for (int mi = 0; mi < 4; mi++) {
                int row = mi * 16 + lr + (quad & 1) * 8;
                int col = kk + (quad >> 1) * 8;
                unsigned addr = (unsigned)__cvta_generic_to_shared(
                    &Asb[row * LDH + col]);
                asm volatile(
                    "ldmatrix.sync.aligned.m8n8.x4.shared.b16 {%0,%1,%2,%3}, [%4];"
                    : "=r"(af[mi][0]), "=r"(af[mi][1]),
                      "=r"(af[mi][2]), "=r"(af[mi][3]) : "r"(addr));
            }
#pragma unroll
            for (int np = 0; np < 2; np++) {
                int row = wn * 32 + np * 16 + lr + (quad & 1) * 8;
                int col = kk + (quad >> 1) * 8;
                unsigned addr = (unsigned)__cvta_generic_to_shared(
                    &Bsb[row * LDH + col]);
                unsigned r0, r1, r2, r3;
                asm volatile(
                    "ldmatrix.sync.aligned.m8n8.x4.shared.b16 {%0,%1,%2,%3}, [%4];"
                    : "=r"(r0), "=r"(r1), "=r"(r2), "=r"(r3) : "r"(addr));
                bf[2 * np + 0][0] = r0; bf[2 * np + 0][1] = r2;
                bf[2 * np + 1][0] = r1; bf[2 * np + 1][1] = r3;
            }
#pragma unroll
            for (int mi = 0; mi < 4; mi++)
#pragma unroll
                for (int ni = 0; ni < 4; ni++)
                    asm volatile(
                        "mma.sync.aligned.m16n8k16.row.col.f32.f16.f16.f32 "
                        "{%0,%1,%2,%3}, {%4,%5,%6,%7}, {%8,%9}, {%0,%1,%2,%3};\n"
                        : "+f"(acc[mi][ni][0]), "+f"(acc[mi][ni][1]),
                          "+f"(acc[mi][ni][2]), "+f"(acc[mi][ni][3])
                        : "r"(af[mi][0]), "r"(af[mi][1]),
                          "r"(af[mi][2]), "r"(af[mi][3]),
                          "r"(bf[ni][0]), "r"(bf[ni][1]));
        }
        buf = (buf + 1) % 3;
        __syncthreads();
    }

#pragma unroll
    for (int mi = 0; mi < 4; mi++) {
#pragma unroll
        for (int ni = 0; ni < 4; ni++) {
            int row = bm0 + mi * 16 + g;
            int col = bn0 + wn * 32 + ni * 8 + 2 * tq;
#pragma unroll
            for (int rr = 0; rr < 2; rr++) {
                int r = row + rr * 8;
                *reinterpret_cast<float2*>(C + (long)r * ldc + col) =
                    make_float2(acc[mi][ni][rr * 2 + 0], acc[mi][ni][rr * 2 + 1]);
            }
        }
    }
}

// ---------------- LSTM activation: gates packed [i | g | o] (3H), fp16 out ------
__global__ void act_lstm(const float* __restrict__ gates,
                         const float* __restrict__ b_ih,
                         const float* __restrict__ b_hh,
                         __half* __restrict__ h, int H, int ldout, long total)
{
    long idx = (long)blockIdx.x * blockDim.x + threadIdx.x;
    if (idx >= total) return;
    int  j = (int)(idx & (H - 1));
    long m = idx / H;
    const float* gr = gates + m * 3 * H;
    float iv = gr[j]         + b_ih[j]         + b_hh[j];
    float gv = gr[H + j]     + b_ih[2 * H + j] + b_hh[2 * H + j];
    float ov = gr[2 * H + j] + b_ih[3 * H + j] + b_hh[3 * H + j];
    float c  = sigf(iv) * tanhf(gv);
    h[m * ldout + j] = __float2half_rn(sigf(ov) * tanhf(c));
}

// =================================================================================
// Fused flash attention (verified R9/R11/R13)
// =================================================================================
#define FA_LD  136
#define FA_QSZ (64 * FA_LD)
#define FA_KSZ (128 * FA_LD)
#define FA_SMEM ((FA_QSZ + 4 * FA_KSZ) * 2)

#define LOAD_KV(sc_, bufi_) do { \
    const __half* ks_ = Km + ((long)b * SN + (sc_) * 128) * KVN; \
    const __half* vs_ = Vm + ((long)b * SN + (sc_) * 128) * KVN; \
    __half* kd_ = Ks + (bufi_) * FA_KSZ; \
    __half* vd_ = Vs + (bufi_) * FA_KSZ; \
    _Pragma("unroll") \
    for (int i_ = 0; i_ < 16; i_++) { \
        int c_ = tid + i_ * 128; \
        int r_ = c_ >> 4, sg_ = c_ & 15; \
        cp16(&kd_[r_ * FA_LD + sg_ * 8], ks_ + r_ * KVN + sg_ * 8); \
        cp16(&vd_[r_ * FA_LD + sg_ * 8], vs_ + r_ * KVN + sg_ * 8); \
    } \
    asm volatile("cp.async.commit_group;" ::: "memory"); \
} while (0)

__global__ void __launch_bounds__(128, 1)
fattn(const __half* __restrict__ Qm,
      const __half* __restrict__ Km,
      const __half* __restrict__ Vm,
      const int* __restrict__ enc_len,
      __half* __restrict__ Om)
{
    extern __shared__ __half sm[];
    __half* Qs = sm;
    __half* Ks = sm + FA_QSZ;
    __half* Vs = Ks + 2 * FA_KSZ;

    const int tid = threadIdx.x;
    const int warp = tid >> 5, lane = tid & 31;
    const int g = lane >> 2, tq = lane & 3;
    const int quad = lane >> 3, lr = lane & 7;
    const int b  = blockIdx.y;
    const int t0 = blockIdx.x * 64;
    const long qrow0 = (long)b * TN + t0;
    const int len = enc_len[b];

#pragma unroll
    for (int i = 0; i < 8; i++) {
        int c = tid + i * 128;
        int r = c >> 4, seg = c & 15;
        cp16(&Qs[r * FA_LD + seg * 8], Qm + (qrow0 + r) * EMBEDN + seg * 8);
    }
    asm volatile("cp.async.commit_group;" ::: "memory");

    LOAD_KV(0, 0);
    LOAD_KV(1, 1);
    asm volatile("cp.async.wait_group 1;" ::: "memory");
    __syncthreads();

    unsigned qf[8][4];
#pragma unroll
    for (int kb = 0; kb < 8; kb++) {
        int row = warp * 16 + lr + (quad & 1) * 8;
        int col = kb * 16 + (quad >> 1) * 8;
        unsigned addr = (unsigned)__cvta_generic_to_shared(&Qs[row * FA_LD + col]);
        asm volatile(
            "ldmatrix.sync.aligned.m8n8.x4.shared.b16 {%0,%1,%2,%3}, [%4];"
            : "=r"(qf[kb][0]), "=r"(qf[kb][1]), "=r"(qf[kb][2]), "=r"(qf[kb][3])
            : "r"(addr));
    }

    float oacc[16][4];
#pragma unroll
    for (int i = 0; i < 16; i++)
#pragma unroll
        for (int q = 0; q < 4; q++) oacc[i][q] = 0.f;
    float m0 = -1e30f, m1 = -1e30f, l0 = 0.f, l1 = 0.f;

    for (int sc = 0; sc < 4; sc++) {
        if (sc == 1 || sc == 2) {
            asm volatile("cp.async.wait_group 1;" ::: "memory");
            __syncthreads();
        } else if (sc == 3) {
            asm volatile("cp.async.wait_group 0;" ::: "memory");
            __syncthreads();
        }
        const __half* Kb = Ks + (sc & 1) * FA_KSZ;
        const __half* Vb = Vs + (sc & 1) * FA_KSZ;

        float eacc[16][4];
#pragma unroll
        for (int i = 0; i < 16; i++)
#pragma unroll
            for (int q = 0; q < 4; q++) eacc[i][q] = 0.f;

#pragma unroll
        for (int kb = 0; kb < 8; kb++) {
#pragma unroll
            for (int np = 0; np < 8; np++) {
                int row = np * 16 + lr + (quad & 1) * 8;
                int col = kb * 16 + (quad >> 1) * 8;
                unsigned addr = (unsigned)__cvta_generic_to_shared(
                    &Kb[row * FA_LD + col]);
                unsigned r0, r1, r2, r3;
                asm volatile(
                    "ldmatrix.sync.aligned.m8n8.x4.shared.b16 {%0,%1,%2,%3}, [%4];"
                    : "=r"(r0), "=r"(r1), "=r"(r2), "=r"(r3) : "r"(addr));
                asm volatile(
                    "mma.sync.aligned.m16n8k16.row.col.f32.f16.f16.f32 "
                    "{%0,%1,%2,%3}, {%4,%5,%6,%7}, {%8,%9}, {%0,%1,%2,%3};\n"
                    : "+f"(eacc[2*np][0]), "+f"(eacc[2*np][1]),
                      "+f"(eacc[2*np][2]), "+f"(eacc[2*np][3])
                    : "r"(qf[kb][0]), "r"(qf[kb][1]), "r"(qf[kb][2]), "r"(qf[kb][3]),
                      "r"(r0), "r"(r2));
                asm volatile(
                    "mma.sync.aligned.m16n8k16.row.col.f32.f16.f16.f32 "
                    "{%0,%1,%2,%3}, {%4,%5,%6,%7}, {%8,%9}, {%0,%1,%2,%3};\n"
                    : "+f"(eacc[2*np+1][0]), "+f"(eacc[2*np+1][1]),
                      "+f"(eacc[2*np+1][2]), "+f"(eacc[2*np+1][3])
                    : "r"(qf[kb][0]), "r"(qf[kb][1]), "r"(qf[kb][2]), "r"(qf[kb][3]),
                      "r"(r1), "r"(r3));
            }
        }

        float mx0 = -1e30f, mx1 = -1e30f;
#pragma unroll
        for (int nb = 0; nb < 16; nb++) {
            int c0 = sc * 128 + nb * 8 + 2 * tq;
            if (c0 >= len)     { eacc[nb][0] = -1e9f; eacc[nb][2] = -1e9f; }
            if (c0 + 1 >= len) { eacc[nb][1] = -1e9f; eacc[nb][3] = -1e9f; }
            mx0 = fmaxf(mx0, fmaxf(eacc[nb][0], eacc[nb][1]));
            mx1 = fmaxf(mx1, fmaxf(eacc[nb][2], eacc[nb][3]));
        }
        mx0 = fmaxf(mx0, __shfl_xor_sync(0xffffffffu, mx0, 1));
        mx0 = fmaxf(mx0, __shfl_xor_sync(0xffffffffu, mx0, 2));
        mx1 = fmaxf(mx1, __shfl_xor_sync(0xffffffffu, mx1, 1));
        mx1 = fmaxf(mx1, __shfl_xor_sync(0xffffffffu, mx1, 2));

        float mn0 = fmaxf(m0, mx0), mn1 = fmaxf(m1, mx1);
        float cf0 = __expf(m0 - mn0), cf1 = __expf(m1 - mn1);
        m0 = mn0; m1 = mn1;
        l0 *= cf0; l1 *= cf1;
#pragma unroll
        for (int nb = 0; nb < 16; nb++) {
            oacc[nb][0] *= cf0; oacc[nb][1] *= cf0;
            oacc[nb][2] *= cf1; oacc[nb][3] *= cf1;
        }

        unsigned pf[16][2];
        float s0 = 0.f, s1 = 0.f;
#pragma unroll
        for (int nb = 0; nb < 16; nb++) {
            float p0 = __expf(eacc[nb][0] - m0);
            float p1 = __expf(eacc[nb][1] - m0);
            float p2 = __expf(eacc[nb][2] - m1);
            float p3 = __expf(eacc[nb][3] - m1);
            s0 += p0 + p1; s1 += p2 + p3;
            __half2 h01 = __floats2half2_rn(p0, p1);
            __half2 h23 = __floats2half2_rn(p2, p3);
            pf[nb][0] = *reinterpret_cast<unsigned*>(&h01);
            pf[nb][1] = *reinterpret_cast<unsigned*>(&h23);
        }
        s0 += __shfl_xor_sync(0xffffffffu, s0, 1);
        s0 += __shfl_xor_sync(0xffffffffu, s0, 2);
        s1 += __shfl_xor_sync(0xffffffffu, s1, 1);
        s1 += __shfl_xor_sync(0xffffffffu, s1, 2);
        l0 += s0; l1 += s1;

#pragma unroll
        for (int kb2 = 0; kb2 < 8; kb2++) {
            unsigned a0 = pf[2*kb2][0], a1 = pf[2*kb2][1];
            unsigned a2 = pf[2*kb2+1][0], a3 = pf[2*kb2+1][1];
#pragma unroll
            for (int vp = 0; vp < 8; vp++) {
                int row = kb2 * 16 + lr + (quad & 1) * 8;
                int col = vp * 16 + (quad >> 1) * 8;
                unsigned addr = (unsigned)__cvta_generic_to_shared(
                    &Vb[row * FA_LD + col]);
                unsigned r0, r1, r2, r3;
                asm volatile(
                    "ldmatrix.sync.aligned.m8n8.x4.trans.shared.b16 {%0,%1,%2,%3}, [%4];"
                    : "=r"(r0), "=r"(r1), "=r"(r2), "=r"(r3) : "r"(addr));
                asm volatile(
                    "mma.sync.aligned.m16n8k16.row.col.f32.f16.f16.f32 "
                    "{%0,%1,%2,%3}, {%4,%5,%6,%7}, {%8,%9}, {%0,%1,%2,%3};\n"
                    : "+f"(oacc[2*vp][0]), "+f"(oacc[2*vp][1]),
                      "+f"(oacc[2*vp][2]), "+f"(oacc[2*vp][3])
                    : "r"(a0), "r"(a1), "r"(a2), "r"(a3), "r"(r0), "r"(r1));
                asm volatile(
                    "mma.sync.aligned.m16n8k16.row.col.f32.f16.f16.f32 "
                    "{%0,%1,%2,%3}, {%4,%5,%6,%7}, {%8,%9}, {%0,%1,%2,%3};\n"
                    : "+f"(oacc[2*vp+1][0]), "+f"(oacc[2*vp+1][1]),
                      "+f"(oacc[2*vp+1][2]), "+f"(oacc[2*vp+1][3])
                    : "r"(a0), "r"(a1), "r"(a2), "r"(a3), "r"(r2), "r"(r3));
            }
        }

        __syncthreads();
        if (sc + 2 < 4) LOAD_KV(sc + 2, sc & 1);
    }

    float inv0 = 1.f / l0, inv1 = 1.f / l1;
    __half* orow0 = Om + (qrow0 + warp * 16 + g) * EMBEDN + KVN;
    __half* orow1 = orow0 + 8 * EMBEDN;
#pragma unroll
    for (int nb = 0; nb < 16; nb++) {
        int c = nb * 8 + 2 * tq;
        __half2 h0 = __floats2half2_rn(oacc[nb][0] * inv0, oacc[nb][1] * inv0);
        __half2 h1 = __floats2half2_rn(oacc[nb][2] * inv1, oacc[nb][3] * inv1);
        *reinterpret_cast<__half2*>(orow0 + c) = h0;
        *reinterpret_cast<__half2*>(orow1 + c) = h1;
    }
}

// ---------------- launch ----------------
extern "C" void kernel_launch(void* const* d_in, const int* in_sizes, int n_in,
                              void* d_out, int out_size)
{
    const float* key   = (const float*)d_in[0];
    const float* value = (const float*)d_in[1];
    const int*   elen  = (const int*)  d_in[2];
    const int*   y     = (const int*)  d_in[3];
    const float* E     = (const float*)d_in[4];
    const float* W1    = (const float*)d_in[5];
    const float* bi1   = (const float*)d_in[6];
    const float* bh1   = (const float*)d_in[7];
    const float* W2    = (const float*)d_in[8];
    const float* bi2   = (const float*)d_in[9];
    const float* bh2   = (const float*)d_in[10];
    const float* bout  = (const float*)d_in[11];
    float*       out   = (float*)d_out;

    float  *gates1, *gates2;
    __half *Eh, *W1h, *W2h, *keyh, *valueh, *h1h, *outctxh;
    cudaGetSymbolAddress((void**)&gates1, g_gates1);
    cudaGetSymbolAddress((void**)&gates2, g_gates2);
    cudaGetSymbolAddress((void**)&Eh,     g_Eh);
    cudaGetSymbolAddress((void**)&W1h,    g_W1h);
    cudaGetSymbolAddress((void**)&W2h,    g_W2h);
    cudaGetSymbolAddress((void**)&keyh,   g_keyh);
    cudaGetSymbolAddress((void**)&valueh, g_valueh);
    cudaGetSymbolAddress((void**)&h1h,    g_h1h);
    cudaGetSymbolAddress((void**)&outctxh,g_outctxh);

    cudaFuncSetAttribute(gemm_h<0>, cudaFuncAttributeMaxDynamicSharedMemorySize, GSMEM);
    cudaFuncSetAttribute(gemm_h<1>, cudaFuncAttributeMaxDynamicSharedMemorySize, GSMEM);
    cudaFuncSetAttribute(gemm_s,    cudaFuncAttributeMaxDynamicSharedMemorySize, S_SMEM);
    cudaFuncSetAttribute(logits_pa, cudaFuncAttributeMaxDynamicSharedMemorySize, PA_SMEM);
    cudaFuncSetAttribute(fattn,     cudaFuncAttributeMaxDynamicSharedMemorySize, FA_SMEM);

    // 0) all fp16 conversions in one launch
    conv_all<<<CONV_TOTAL / 256, 256>>>(
        (const float4*)E, (const float4*)W1, (const float4*)W2,
        (const float4*)key, (const float4*)value,
        (uint2*)Eh, (uint2*)W1h, (uint2*)W2h, (uint2*)keyh, (uint2*)valueh);

    // 1) gates1 = embed(tokens) @ W1'^T    (M=8192, N=1536, K=256)
    gemm_h<1><<<dim3(1536 / GBN, MROWS / GBM), 256, GSMEM>>>(
        Eh, W1h, gates1, EMBEDN, EMBEDN, EMBEDN, 3 * H1N, y);

    // 2) h1 = lstm_act(gates1) -> fp16
    {
        long total = (long)MROWS * H1N;
        act_lstm<<<(unsigned)((total + 255) / 256), 256>>>(
            gates1, bi1, bh1, h1h, H1N, H1N, total);
    }

    // 3) gates2 = h1 @ W2'^T   (M=8192, N=384, K=512), 384 CTAs
    gemm_s<<<dim3(384 / 128, MROWS / 64), 128, S_SMEM>>>(
        h1h, W2h, gates2, H1N, H1N, H1N, 3 * KVN);

    // 4) h2 = lstm_act(gates2) -> outctx[:, 0:128]
    {
        long total = (long)MROWS * KVN;
        act_lstm<<<(unsigned)((total + 255) / 256), 256>>>(
            gates2, bi2, bh2, outctxh, KVN, EMBEDN, total);
    }

    // 5) fused attention -> outctx[:, 128:256]
    fattn<<<dim3(TN / 64, BN_), 128, FA_SMEM>>>(
        outctxh, keyh, valueh, elen, outctxh);

    // 6) logits = E @ out_ctx^T + b_out -> out[b][v][t]  (M-tile 256)
    logits_pa<<<dim3((MROWS / 128) / PA_NT, VOCABN / 256), 256, PA_SMEM>>>(
        Eh, outctxh, bout, out);

    (void)in_sizes; (void)n_in; (void)out_size;
}

// round 16
// speedup vs baseline: 1.0283x; 1.0283x over previous
#include <cuda_runtime.h>
#include <cuda_fp16.h>
#include <cstdint>

#define VOCABN 32000
#define EMBEDN 256
#define H1N    512
#define KVN    128
#define BN_    32
#define SN     512
#define TN     256
#define MROWS  (BN_*TN)   // 8192

// ---------------- scratch (static device globals; no allocation) ----------------
__device__ float  g_gates1[MROWS * 3 * H1N];
__device__ float  g_gates2[MROWS * 3 * KVN];
__device__ __half g_Eh  [VOCABN * EMBEDN];
__device__ __half g_W1h [3 * H1N * EMBEDN];
__device__ __half g_W2h [3 * KVN * H1N];
__device__ __half g_keyh[BN_ * SN * KVN];
__device__ __half g_valueh[BN_ * SN * KVN];
__device__ __half g_h1h [MROWS * H1N];
__device__ __half g_outctxh[MROWS * EMBEDN];

// ---------------- helpers ----------------
__device__ __forceinline__ void cp16(void* dst_smem, const void* src) {
    unsigned s = (unsigned)__cvta_generic_to_shared(dst_smem);
    asm volatile("cp.async.cg.shared.global [%0], [%1], 16;" :: "r"(s), "l"(src));
}
__device__ __forceinline__ float sigf(float x) { return 1.f / (1.f + expf(-x)); }

// ---------------- one-shot fp32->fp16 conversion for ALL operands ----------------
__global__ void conv_all(const float4* __restrict__ E,  const float4* __restrict__ W1,
                         const float4* __restrict__ W2, const float4* __restrict__ key,
                         const float4* __restrict__ value,
                         uint2* __restrict__ Eh,  uint2* __restrict__ W1h,
                         uint2* __restrict__ W2h, uint2* __restrict__ keyh,
                         uint2* __restrict__ valueh)
{
    const long nE   = (long)VOCABN * EMBEDN / 4;
    const long nW1g = H1N * EMBEDN / 4;
    const long nW2g = KVN * H1N / 4;
    const long nKey = (long)BN_ * SN * KVN / 4;

    long o = (long)blockIdx.x * blockDim.x + threadIdx.x;
    const float4* src; uint2* dst; long si, di;
    if (o < nE) { src = E; dst = Eh; si = o; di = o; }
    else {
        o -= nE;
        if (o < 3 * nW1g) {
            long gate = o >> 15, r = o & (nW1g - 1);
            long sg = (gate == 0) ? 0 : gate + 1;
            src = W1; dst = W1h; si = sg * nW1g + r; di = o;
        } else {
            o -= 3 * nW1g;
            if (o < 3 * nW2g) {
                long gate = o >> 14, r = o & (nW2g - 1);
                long sg = (gate == 0) ? 0 : gate + 1;
                src = W2; dst = W2h; si = sg * nW2g + r; di = o;
            } else {
                o -= 3 * nW2g;
                if (o < nKey) { src = key; dst = keyh; si = o; di = o; }
                else {
                    o -= nKey;
                    if (o >= nKey) return;
                    src = value; dst = valueh; si = o; di = o;
                }
            }
        }
    }
    float4 v = src[si];
    __half2 h0 = __floats2half2_rn(v.x, v.y);
    __half2 h1 = __floats2half2_rn(v.z, v.w);
    uint2 out;
    out.x = *reinterpret_cast<unsigned*>(&h0);
    out.y = *reinterpret_cast<unsigned*>(&h1);
    dst[di] = out;
}
#define CONV_TOTAL (2048000 + 3*32768 + 3*16384 + 524288 + 524288)

// =================================================================================
// PERSISTENT-A logits GEMM v3 (verified R11/R13): 4 warps (2m x 2n), warp tile
// 64x64, 128 threads, 2 CTAs/SM. A resident XOR-swizzled; 3-slot B ring;
// single sync/chunk; .cs stores. PA_NT=16: A prologue amortized over 16 n-tiles.
// =================================================================================
#define PA_NT  16
#define A_STR  256
#define A_SMH  (128 * A_STR)
#define B_STR  64
#define B_SLOT (128 * B_STR)
#define PA_SMEM ((A_SMH + 3 * B_SLOT) * 2)

__global__ void __launch_bounds__(128, 2)
logits_pa(const __half* __restrict__ Eh, const __half* __restrict__ Bm,
          const float* __restrict__ bias, float* __restrict__ out)
{
    extern __shared__ __half sh[];
    __half* Ash = sh;
    __half* Bsh = sh + A_SMH;

    const int tid  = threadIdx.x;
    const int warp = tid >> 5, lane = tid & 31;
    const int wm = warp >> 1, wn = warp & 1;
    const int g  = lane >> 2, tq = lane & 3;
    const int quad = lane >> 3, lr = lane & 7;
    const int bm0 = blockIdx.y * 128;
    const int nt0 = blockIdx.x * PA_NT;

#pragma unroll
    for (int i = 0; i < 32; i++) {
        int c = tid + i * 128;
        int r = c >> 5, seg = c & 31;
        int segw = (seg & ~7) | ((seg & 7) ^ (r & 7));
        cp16(&Ash[r * A_STR + segw * 8], Eh + (long)(bm0 + r) * EMBEDN + seg * 8);
    }
    asm volatile("cp.async.commit_group;" ::: "memory");

    int rB[8], sB[8], swB[8];
#pragma unroll
    for (int i = 0; i < 8; i++) {
        int c = tid + i * 128;
        rB[i] = c >> 3; sB[i] = c & 7;
        swB[i] = sB[i] ^ (rB[i] & 7);
    }
#pragma unroll
    for (int p = 0; p < 2; p++) {
        const __half* src = Bm + (long)(nt0 * 128) * EMBEDN + p * 64;
#pragma unroll
        for (int i = 0; i < 8; i++)
            cp16(&Bsh[p * B_SLOT + rB[i] * B_STR + swB[i] * 8],
                 src + (long)rB[i] * EMBEDN + sB[i] * 8);
        asm volatile("cp.async.commit_group;" ::: "memory");
    }

    float bb[8];
#pragma unroll
    for (int mi = 0; mi < 4; mi++)
#pragma unroll
        for (int rr = 0; rr < 2; rr++)
            bb[mi * 2 + rr] = bias[bm0 + wm * 64 + mi * 16 + g + rr * 8];

    float acc[4][8][4];
#pragma unroll
    for (int i = 0; i < 4; i++)
#pragma unroll
        for (int j = 0; j < 8; j++)
#pragma unroll
            for (int q = 0; q < 4; q++) acc[i][j][q] = 0.f;

    const int NCH = PA_NT * 4;
    int slot = 0;
    for (int gch = 0; gch < NCH; gch++) {
        if (gch == NCH - 1) {
            asm volatile("cp.async.wait_group 0;" ::: "memory");
        } else {
            asm volatile("cp.async.wait_group 1;" ::: "memory");
        }
        __syncthreads();

        if (gch + 2 < NCH) {
            int g2 = gch + 2;
            int nt = g2 >> 2, kc = g2 & 3;
            int s2 = g2 % 3;
            const __half* src = Bm + (long)((nt0 + nt) * 128) * EMBEDN + kc * 64;
#pragma unroll
            for (int i = 0; i < 8; i++)
                cp16(&Bsh[s2 * B_SLOT + rB[i] * B_STR + swB[i] * 8],
                     src + (long)rB[i] * EMBEDN + sB[i] * 8);
            asm volatile("cp.async.commit_group;" ::: "memory");
        }

        const __half* Bslot = Bsh + slot * B_SLOT;
        const int kbase = (gch & 3) * 64;

#pragma unroll
        for (int kk = 0; kk < 64; kk += 16) {
            unsigned af[4][4], bf[8][2];
#pragma unroll
            for (int mi = 0; mi < 4; mi++) {
                int row = wm * 64 + mi * 16 + lr + (quad & 1) * 8;
                int seg = ((kbase + kk) >> 3) + (quad >> 1);
                int segw = (seg & ~7) | ((seg & 7) ^ (row & 7));
                unsigned addr = (unsigned)__cvta_generic_to_shared(
                    &Ash[row * A_STR + segw * 8]);
                asm volatile(
                    "ldmatrix.sync.aligned.m8n8.x4.shared.b16 {%0,%1,%2,%3}, [%4];"
                    : "=r"(af[mi][0]), "=r"(af[mi][1]),
                      "=r"(af[mi][2]), "=r"(af[mi][3]) : "r"(addr));
            }
#pragma unroll
            for (int np = 0; np < 4; np++) {
                int row = wn * 64 + np * 16 + lr + (quad & 1) * 8;
                int seg = (kk >> 3) + (quad >> 1);
                int segw = seg ^ (row & 7);
                unsigned addr = (unsigned)__cvta_generic_to_shared(
                    &Bslot[row * B_STR + segw * 8]);
                unsigned r0, r1, r2, r3;
                asm volatile(
                    "ldmatrix.sync.aligned.m8n8.x4.shared.b16 {%0,%1,%2,%3}, [%4];"
                    : "=r"(r0), "=r"(r1), "=r"(r2), "=r"(r3) : "r"(addr));
                bf[2 * np + 0][0] = r0; bf[2 * np + 0][1] = r2;
                bf[2 * np + 1][0] = r1; bf[2 * np + 1][1] = r3;
            }
#pragma unroll
            for (int mi = 0; mi < 4; mi++)
#pragma unroll
                for (int ni = 0; ni < 8; ni++)
                    asm volatile(
                        "mma.sync.aligned.m16n8k16.row.col.f32.f16.f16.f32 "
                        "{%0,%1,%2,%3}, {%4,%5,%6,%7}, {%8,%9}, {%0,%1,%2,%3};\n"
                        : "+f"(acc[mi][ni][0]), "+f"(acc[mi][ni][1]),
                          "+f"(acc[mi][ni][2]), "+f"(acc[mi][ni][3])
                        : "r"(af[mi][0]), "r"(af[mi][1]),
                          "r"(af[mi][2]), "r"(af[mi][3]),
                          "r"(bf[ni][0]), "r"(bf[ni][1]));
        }
        slot = (slot + 1 == 3) ? 0 : slot + 1;

        if ((gch & 3) == 3) {
            int ncol0 = (nt0 + (gch >> 2)) * 128;
#pragma unroll
            for (int mi = 0; mi < 4; mi++) {
#pragma unroll
                for (int ni = 0; ni < 8; ni++) {
                    int row = bm0 + wm * 64 + mi * 16 + g;
                    int col = ncol0 + wn * 64 + ni * 8 + 2 * tq;
                    int bidx = col >> 8;
                    int t    = col & 255;
#pragma unroll
                    for (int rr = 0; rr < 2; rr++) {
                        int r = row + rr * 8;
                        float v0 = acc[mi][ni][rr * 2 + 0] + bb[mi * 2 + rr];
                        float v1 = acc[mi][ni][rr * 2 + 1] + bb[mi * 2 + rr];
                        __stcs(reinterpret_cast<float2*>(
                                   out + (long)bidx * VOCABN * TN + (long)r * TN + t),
                               make_float2(v0, v1));
                        acc[mi][ni][rr * 2 + 0] = 0.f;
                        acc[mi][ni][rr * 2 + 1] = 0.f;
                    }
                }
            }
        }
    }
}

// =================================================================================
// fp16 TN GEMM, CTA 128x128, BK=64, 3-stage cp.async (verified R7/R8/R13)
// MODE 0: plain | MODE 1: token-gather A
// =================================================================================
#define GBM 128
#define GBN 128
#define GBK 64
#define LDH 72
#define TSTG (128 * LDH)
#define STGH (2 * TSTG)
#define GSMEM (3 * STGH * 2)

template <int MODE>
__global__ void __launch_bounds__(256, 2)
gemm_h(const __half* __restrict__ A, const __half* __restrict__ Bmat,
       float* __restrict__ C,
       int K, int lda, int ldb, int ldc,
       const int* __restrict__ ytok)
{
    extern __shared__ __half sh[];

    const int tid  = threadIdx.x;
    const int warp = tid >> 5, lane = tid & 31;
    const int wm = warp >> 2, wn = warp & 3;
    const int g  = lane >> 2, tq = lane & 3;
    const int quad = lane >> 3, lr = lane & 7;
    const int bm0 = blockIdx.y * GBM;
    const int bn0 = blockIdx.x * GBN;

    int rA[4], sA_[4];
    const __half* srcA[4];
    const __half* srcB[4];
#pragma unroll
    for (int i = 0; i < 4; i++) {
        int c   = tid + i * 256;
        int r   = c >> 3;
        int seg = c & 7;
        rA[i] = r; sA_[i] = seg;
        if (MODE == 1) {
            int m   = bm0 + r;
            int tok = ((m & (TN - 1)) == 0) ? 0 : ytok[m - 1];
            srcA[i] = A + (long)tok * lda + seg * 8;
        } else {
            srcA[i] = A + (long)(bm0 + r) * lda + seg * 8;
        }
        srcB[i] = Bmat + (long)(bn0 + r) * ldb + seg * 8;
    }

    float acc[4][4][4];
#pragma unroll
    for (int i = 0; i < 4; i++)
#pragma unroll
        for (int j = 0; j < 4; j++)
#pragma unroll
            for (int q = 0; q < 4; q++) acc[i][j][q] = 0.f;

    const int nt = K / GBK;

#pragma unroll
    for (int s = 0; s < 2; s++) {
        if (s < nt) {
            __half* Ad = sh + s * STGH;
            __half* Bd = Ad + TSTG;
            int k0 = s * GBK;
#pragma unroll
            for (int i = 0; i < 4; i++) {
                cp16(&Ad[rA[i] * LDH + sA_[i] * 8], srcA[i] + k0);
                cp16(&Bd[rA[i] * LDH + sA_[i] * 8], srcB[i] + k0);
            }
            asm volatile("cp.async.commit_group;" ::: "memory");
        }
    }

    int buf = 0;
    for (int kt = 0; kt < nt; kt++) {
        if (kt + 1 < nt) {
            asm volatile("cp.async.wait_group 1;" ::: "memory");
        } else {
            asm volatile("cp.async.wait_group 0;" ::: "memory");
        }
        __syncthreads();

        if (kt + 2 < nt) {
            int sb2 = (kt + 2) % 3;
            __half* Ad = sh + sb2 * STGH;
            __half* Bd = Ad + TSTG;
            int k0 = (kt + 2) * GBK;
#pragma unroll
            for (int i = 0; i < 4; i++) {
                cp16(&Ad[rA[i] * LDH + sA_[i] * 8], srcA[i] + k0);
                cp16(&Bd[rA[i] * LDH + sA_[i] * 8], srcB[i] + k0);
            }
            asm volatile("cp.async.commit_group;" ::: "memory");
        }

        const __half* Asb = sh + buf * STGH;
        const __half* Bsb = Asb + TSTG;

#pragma unroll
        for (int kk = 0; kk < GBK; kk += 16) {
            unsigned af[4][4], bf[4][2];
#pragma unroll
            for (int mi = 0; mi < 4; mi++) {
                int row = wm * 64 + mi * 16 + lr + (quad & 1) * 8;
                int col = kk + (quad >> 1) * 8;
                unsigned addr = (unsigned)__cvta_generic_to_shared(
                    &Asb[row * LDH + col]);
                asm volatile(
                    "ldmatrix.sync.aligned.m8n8.x4.shared.b16 {%0,%1,%2,%3}, [%4];"
                    : "=r"(af[mi][0]), "=r"(af[mi][1]),
                      "=r"(af[mi][2]), "=r"(af[mi][3]) : "r"(addr));
            }
#pragma unroll
            for (int np = 0; np < 2; np++) {
                int row = wn * 32 + np * 16 + lr + (quad & 1) * 8;
                int col = kk + (quad >> 1) * 8;
                unsigned addr = (unsigned)__cvta_generic_to_shared(
                    &Bsb[row * LDH + col]);
                unsigned r0, r1, r2, r3;
                asm volatile(
                    "ldmatrix.sync.aligned.m8n8.x4.shared.b16 {%0,%1,%2,%3}, [%4];"
                    : "=r"(r0), "=r"(r1), "=r"(r2), "=r"(r3) : "r"(addr));
                bf[2 * np + 0][0] = r0; bf[2 * np + 0][1] = r2;
                bf[2 * np + 1][0] = r1; bf[2 * np + 1][1] = r3;
            }
#pragma unroll
            for (int mi = 0; mi < 4; mi++)
#pragma unroll
                for (int ni = 0; ni < 4; ni++)
                    asm volatile(
                        "mma.sync.aligned.m16n8k16.row.col.f32.f16.f16.f32 "
                        "{%0,%1,%2,%3}, {%4,%5,%6,%7}, {%8,%9}, {%0,%1,%2,%3};\n"
                        : "+f"(acc[mi][ni][0]), "+f"(acc[mi][ni][1]),
                          "+f"(acc[mi][ni][2]), "+f"(acc[mi][ni][3])
                        : "r"(af[mi][0]), "r"(af[mi][1]),
                          "r"(af[mi][2]), "r"(af[mi][3]),
                          "r"(bf[ni][0]), "r"(bf[ni][1]));
        }
        buf = (buf + 1) % 3;
        __syncthreads();
    }

#pragma unroll
    for (int mi = 0; mi < 4; mi++) {
#pragma unroll
        for (int ni = 0; ni < 4; ni++) {
            int row = bm0 + wm * 64 + mi * 16 + g;
            int col = bn0 + wn * 32 + ni * 8 + 2 * tq;
#pragma unroll
            for (int rr = 0; rr < 2; rr++) {
                int r = row + rr * 8;
                *reinterpret_cast<float2*>(C + (long)r * ldc + col) =
                    make_float2(acc[mi][ni][rr * 2 + 0], acc[mi][ni][rr * 2 + 1]);
            }
        }
    }
}

// =================================================================================
// SMALL-M fp16 TN GEMM for gates2 (verified R12/R13): CTA 64x128, 128 threads.
// =================================================================================
#define S_ASTG (64 * LDH)
#define S_BSTG (128 * LDH)
#define S_STG  (S_ASTG + S_BSTG)
#define S_SMEM (3 * S_STG * 2)

__global__ void __launch_bounds__(128, 2)
gemm_s(const __half* __restrict__ A, const __half* __restrict__ Bmat,
       float* __restrict__ C, int K, int lda, int ldb, int ldc)
{
    extern __shared__ __half sh[];

    const int tid  = threadIdx.x;
    const int warp = tid >> 5, lane = tid & 31;
    const int wn = warp;
    const int g  = lane >> 2, tq = lane & 3;
    const int quad = lane >> 3, lr = lane & 7;
    const int bm0 = blockIdx.y * 64;
    const int bn0 = blockIdx.x * 128;

    int rA[4], sA_[4];
    const __half* srcA[4];
#pragma unroll
    for (int i = 0; i < 4; i++) {
        int c = tid + i * 128;
        rA[i] = c >> 3; sA_[i] = c & 7;
        srcA[i] = A + (long)(bm0 + rA[i]) * lda + sA_[i] * 8;
    }
    int rBs[8], sBs[8];
    const __half* srcB[8];
#pragma unroll
    for (int i = 0; i < 8; i++) {
        int c = tid + i * 128;
        rBs[i] = c >> 3; sBs[i] = c & 7;
        srcB[i] = Bmat + (long)(bn0 + rBs[i]) * ldb + sBs[i] * 8;
    }

    float acc[4][4][4];
#pragma unroll
    for (int i = 0; i < 4; i++)
#pragma unroll
        for (int j = 0; j < 4; j++)
#pragma unroll
            for (int q = 0; q < 4; q++) acc[i][j][q] = 0.f;

    const int nt = K / GBK;

#pragma unroll
    for (int s = 0; s < 2; s++) {
        __half* Ad = sh + s * S_STG;
        __half* Bd = Ad + S_ASTG;
        int k0 = s * GBK;
#pragma unroll
        for (int i = 0; i < 4; i++)
            cp16(&Ad[rA[i] * LDH + sA_[i] * 8], srcA[i] + k0);
#pragma unroll
        for (int i = 0; i < 8; i++)
            cp16(&Bd[rBs[i] * LDH + sBs[i] * 8], srcB[i] + k0);
        asm volatile("cp.async.commit_group;" ::: "memory");
    }

    int buf = 0;
    for (int kt = 0; kt < nt; kt++) {
        if (kt + 1 < nt) {
            asm volatile("cp.async.wait_group 1;" ::: "memory");
        } else {
            asm volatile("cp.async.wait_group 0;" ::: "memory");
        }
        __syncthreads();

        if (kt + 2 < nt) {
            int sb2 = (kt + 2) % 3;
            __half* Ad = sh + sb2 * S_STG;
            __half* Bd = Ad + S_ASTG;
            int k0 = (kt + 2) * GBK;
#pragma unroll
            for (int i = 0; i < 4; i++)
                cp16(&Ad[rA[i] * LDH + sA_[i] * 8], srcA[i] + k0);
#pragma unroll
            for (int i = 0; i < 8; i++)
                cp16(&Bd[rBs[i] * LDH + sBs[i] * 8], srcB[i] + k0);
            asm volatile("cp.async.commit_group;" ::: "memory");
        }

        const __half* Asb = sh + buf * S_STG;
        const __half* Bsb = Asb + S_ASTG;

#pragma unroll
        for (int kk = 0; kk < GBK; kk += 16) {
            unsigned af[4][4], bf[4][2];
#pragma unroll
            for (int mi = 0; mi < 4; mi++) {
                int row = mi * 16 + lr + (quad & 1) * 8;
                int col = kk + (quad >> 1) * 8;
                unsigned addr = (unsigned)__cvta_generic_to_shared(
                    &Asb[row * LDH + col]);
                asm volatile(
                    "ldmatrix.sync.aligned.m8n8.x4.shared.b16 {%0,%1,%2,%3}, [%4];"
                    : "=r"(af[mi][0]), "=r"(af[mi][1]),
                      "=r"(af[mi][2]), "=r"(af[mi][3]) : "r"(addr));
            }
#pragma unroll
            for (int np = 0; np < 2; np++) {
                int row = wn * 32 + np * 16 + lr + (quad & 1) * 8;
                int col = kk + (quad >> 1) * 8;
                unsigned addr = (unsigned)__cvta_generic_to_shared(
                    &Bsb[row * LDH + col]);
                unsigned r0, r1, r2, r3;
                asm volatile(
                    "ldmatrix.sync.aligned.m8n8.x4.shared.b16 {%0,%1,%2,%3}, [%4];"
                    : "=r"(r0), "=r"(r1), "=r"(r2), "=r"(r3) : "r"(addr));
                bf[2 * np + 0][0] = r0; bf[2 * np + 0][1] = r2;
                bf[2 * np + 1][0] = r1; bf[2 * np + 1][1] = r3;
            }
#pragma unroll
            for (int mi = 0; mi < 4; mi++)
#pragma unroll
                for (int ni = 0; ni < 4; ni++)
                    asm volatile(
                        "mma.sync.aligned.m16n8k16.row.col.f32.f16.f16.f32 "
                        "{%0,%1,%2,%3}, {%4,%5,%6,%7}, {%8,%9}, {%0,%1,%2,%3};\n"
                        : "+f"(acc[mi][ni][0]), "+f"(acc[mi][ni][1]),
                          "+f"(acc[mi][ni][2]), "+f"(acc[mi][ni][3])
                        : "r"(af[mi][0]), "r"(af[mi][1]),
                          "r"(af[mi][2]), "r"(af[mi][3]),
                          "r"(bf[ni][0]), "r"(bf[ni][1]));
        }
        buf = (buf + 1) % 3;
        __syncthreads();
    }

#pragma unroll
    for (int mi = 0; mi < 4; mi++) {
#pragma unroll
        for (int ni = 0; ni < 4; ni++) {
            int row = bm0 + mi * 16 + g;
            int col = bn0 + wn * 32 + ni * 8 + 2 * tq;
#pragma unroll
            for (int rr = 0; rr < 2; rr++) {
                int r = row + rr * 8;
                *reinterpret_cast<float2*>(C + (long)r * ldc + col) =
                    make_float2(acc[mi][ni][rr * 2 + 0], acc[mi][ni][rr * 2 + 1]);
            }
        }
    }
}

// ---------------- LSTM activation: gates packed [i | g | o] (3H), fp16 out ------
__global__ void act_lstm(const float* __restrict__ gates,
                         const float* __restrict__ b_ih,
                         const float* __restrict__ b_hh,
                         __half* __restrict__ h, int H, int ldout, long total)
{
    long idx = (long)blockIdx.x * blockDim.x + threadIdx.x;
    if (idx >= total) return;
    int  j = (int)(idx & (H - 1));
    long m = idx / H;
    const float* gr = gates + m * 3 * H;
    float iv = gr[j]         + b_ih[j]         + b_hh[j];
    float gv = gr[H + j]     + b_ih[2 * H + j] + b_hh[2 * H + j];
    float ov = gr[2 * H + j] + b_ih[3 * H + j] + b_hh[3 * H + j];
    float c  = sigf(iv) * tanhf(gv);
    h[m * ldout + j] = __float2half_rn(sigf(ov) * tanhf(c));
}

// =================================================================================
// Fused flash attention (verified R9/R11/R13)
// =================================================================================
#define FA_LD  136
#define FA_QSZ (64 * FA_LD)
#define FA_KSZ (128 * FA_LD)
#define FA_SMEM ((FA_QSZ + 4 * FA_KSZ) * 2)

#define LOAD_KV(sc_, bufi_) do { \
    const __half* ks_ = Km + ((long)b * SN + (sc_) * 128) * KVN; \
    const __half* vs_ = Vm + ((long)b * SN + (sc_) * 128) * KVN; \
    __half* kd_ = Ks + (bufi_) * FA_KSZ; \
    __half* vd_ = Vs + (bufi_) * FA_KSZ; \
    _Pragma("unroll") \
    for (int i_ = 0; i_ < 16; i_++) { \
        int c_ = tid + i_ * 128; \
        int r_ = c_ >> 4, sg_ = c_ & 15; \
        cp16(&kd_[r_ * FA_LD + sg_ * 8], ks_ + r_ * KVN + sg_ * 8); \
        cp16(&vd_[r_ * FA_LD + sg_ * 8], vs_ + r_ * KVN + sg_ * 8); \
    } \
    asm volatile("cp.async.commit_group;" ::: "memory"); \
} while (0)

__global__ void __launch_bounds__(128, 1)
fattn(const __half* __restrict__ Qm,
      const __half* __restrict__ Km,
      const __half* __restrict__ Vm,
      const int* __restrict__ enc_len,
      __half* __restrict__ Om)
{
    extern __shared__ __half sm[];
    __half* Qs = sm;
    __half* Ks = sm + FA_QSZ;
    __half* Vs = Ks + 2 * FA_KSZ;

    const int tid = threadIdx.x;
    const int warp = tid >> 5, lane = tid & 31;
    const int g = lane >> 2, tq = lane & 3;
    const int quad = lane >> 3, lr = lane & 7;
    const int b  = blockIdx.y;
    const int t0 = blockIdx.x * 64;
    const long qrow0 = (long)b * TN + t0;
    const int len = enc_len[b];

#pragma unroll
    for (int i = 0; i < 8; i++) {
        int c = tid + i * 128;
        int r = c >> 4, seg = c & 15;
        cp16(&Qs[r * FA_LD + seg * 8], Qm + (qrow0 + r) * EMBEDN + seg * 8);
    }
    asm volatile("cp.async.commit_group;" ::: "memory");

    LOAD_KV(0, 0);
    LOAD_KV(1, 1);
    asm volatile("cp.async.wait_group 1;" ::: "memory");
    __syncthreads();

    unsigned qf[8][4];
#pragma unroll
    for (int kb = 0; kb < 8; kb++) {
        int row = warp * 16 + lr + (quad & 1) * 8;
        int col = kb * 16 + (quad >> 1) * 8;
        unsigned addr = (unsigned)__cvta_generic_to_shared(&Qs[row * FA_LD + col]);
        asm volatile(
            "ldmatrix.sync.aligned.m8n8.x4.shared.b16 {%0,%1,%2,%3}, [%4];"
            : "=r"(qf[kb][0]), "=r"(qf[kb][1]), "=r"(qf[kb][2]), "=r"(qf[kb][3])
            : "r"(addr));
    }

    float oacc[16][4];
#pragma unroll
    for (int i = 0; i < 16; i++)
#pragma unroll
        for (int q = 0; q < 4; q++) oacc[i][q] = 0.f;
    float m0 = -1e30f, m1 = -1e30f, l0 = 0.f, l1 = 0.f;

    for (int sc = 0; sc < 4; sc++) {
        if (sc == 1 || sc == 2) {
            asm volatile("cp.async.wait_group 1;" ::: "memory");
            __syncthreads();
        } else if (sc == 3) {
            asm volatile("cp.async.wait_group 0;" ::: "memory");
            __syncthreads();
        }
        const __half* Kb = Ks + (sc & 1) * FA_KSZ;
        const __half* Vb = Vs + (sc & 1) * FA_KSZ;

        float eacc[16][4];
#pragma unroll
        for (int i = 0; i < 16; i++)
#pragma unroll
            for (int q = 0; q < 4; q++) eacc[i][q] = 0.f;

#pragma unroll
        for (int kb = 0; kb < 8; kb++) {
#pragma unroll
            for (int np = 0; np < 8; np++) {
                int row = np * 16 + lr + (quad & 1) * 8;
                int col = kb * 16 + (quad >> 1) * 8;
                unsigned addr = (unsigned)__cvta_generic_to_shared(
                    &Kb[row * FA_LD + col]);
                unsigned r0, r1, r2, r3;
                asm volatile(
                    "ldmatrix.sync.aligned.m8n8.x4.shared.b16 {%0,%1,%2,%3}, [%4];"
                    : "=r"(r0), "=r"(r1), "=r"(r2), "=r"(r3) : "r"(addr));
                asm volatile(
                    "mma.sync.aligned.m16n8k16.row.col.f32.f16.f16.f32 "
                    "{%0,%1,%2,%3}, {%4,%5,%6,%7}, {%8,%9}, {%0,%1,%2,%3};\n"
                    : "+f"(eacc[2*np][0]), "+f"(eacc[2*np][1]),
                      "+f"(eacc[2*np][2]), "+f"(eacc[2*np][3])
                    : "r"(qf[kb][0]), "r"(qf[kb][1]), "r"(qf[kb][2]), "r"(qf[kb][3]),
                      "r"(r0), "r"(r2));
                asm volatile(
                    "mma.sync.aligned.m16n8k16.row.col.f32.f16.f16.f32 "
                    "{%0,%1,%2,%3}, {%4,%5,%6,%7}, {%8,%9}, {%0,%1,%2,%3};\n"
                    : "+f"(eacc[2*np+1][0]), "+f"(eacc[2*np+1][1]),
                      "+f"(eacc[2*np+1][2]), "+f"(eacc[2*np+1][3])
                    : "r"(qf[kb][0]), "r"(qf[kb][1]), "r"(qf[kb][2]), "r"(qf[kb][3]),
                      "r"(r1), "r"(r3));
            }
        }

        float mx0 = -1e30f, mx1 = -1e30f;
#pragma unroll
        for (int nb = 0; nb < 16; nb++) {
            int c0 = sc * 128 + nb * 8 + 2 * tq;
            if (c0 >= len)     { eacc[nb][0] = -1e9f; eacc[nb][2] = -1e9f; }
            if (c0 + 1 >= len) { eacc[nb][1] = -1e9f; eacc[nb][3] = -1e9f; }
            mx0 = fmaxf(mx0, fmaxf(eacc[nb][0], eacc[nb][1]));
            mx1 = fmaxf(mx1, fmaxf(eacc[nb][2], eacc[nb][3]));
        }
        mx0 = fmaxf(mx0, __shfl_xor_sync(0xffffffffu, mx0, 1));
        mx0 = fmaxf(mx0, __shfl_xor_sync(0xffffffffu, mx0, 2));
        mx1 = fmaxf(mx1, __shfl_xor_sync(0xffffffffu, mx1, 1));
        mx1 = fmaxf(mx1, __shfl_xor_sync(0xffffffffu, mx1, 2));

        float mn0 = fmaxf(m0, mx0), mn1 = fmaxf(m1, mx1);
        float cf0 = __expf(m0 - mn0), cf1 = __expf(m1 - mn1);
        m0 = mn0; m1 = mn1;
        l0 *= cf0; l1 *= cf1;
#pragma unroll
        for (int nb = 0; nb < 16; nb++) {
            oacc[nb][0] *= cf0; oacc[nb][1] *= cf0;
            oacc[nb][2] *= cf1; oacc[nb][3] *= cf1;
        }

        unsigned pf[16][2];
        float s0 = 0.f, s1 = 0.f;
#pragma unroll
        for (int nb = 0; nb < 16; nb++) {
            float p0 = __expf(eacc[nb][0] - m0);
            float p1 = __expf(eacc[nb][1] - m0);
            float p2 = __expf(eacc[nb][2] - m1);
            float p3 = __expf(eacc[nb][3] - m1);
            s0 += p0 + p1; s1 += p2 + p3;
            __half2 h01 = __floats2half2_rn(p0, p1);
            __half2 h23 = __floats2half2_rn(p2, p3);
            pf[nb][0] = *reinterpret_cast<unsigned*>(&h01);
            pf[nb][1] = *reinterpret_cast<unsigned*>(&h23);
        }
        s0 += __shfl_xor_sync(0xffffffffu, s0, 1);
        s0 += __shfl_xor_sync(0xffffffffu, s0, 2);
        s1 += __shfl_xor_sync(0xffffffffu, s1, 1);
        s1 += __shfl_xor_sync(0xffffffffu, s1, 2);
        l0 += s0; l1 += s1;

#pragma unroll
        for (int kb2 = 0; kb2 < 8; kb2++) {
            unsigned a0 = pf[2*kb2][0], a1 = pf[2*kb2][1];
            unsigned a2 = pf[2*kb2+1][0], a3 = pf[2*kb2+1][1];
#pragma unroll
            for (int vp = 0; vp < 8; vp++) {
                int row = kb2 * 16 + lr + (quad & 1) * 8;
                int col = vp * 16 + (quad >> 1) * 8;
                unsigned addr = (unsigned)__cvta_generic_to_shared(
                    &Vb[row * FA_LD + col]);
                unsigned r0, r1, r2, r3;
                asm volatile(
                    "ldmatrix.sync.aligned.m8n8.x4.trans.shared.b16 {%0,%1,%2,%3}, [%4];"
                    : "=r"(r0), "=r"(r1), "=r"(r2), "=r"(r3) : "r"(addr));
                asm volatile(
                    "mma.sync.aligned.m16n8k16.row.col.f32.f16.f16.f32 "
                    "{%0,%1,%2,%3}, {%4,%5,%6,%7}, {%8,%9}, {%0,%1,%2,%3};\n"
                    : "+f"(oacc[2*vp][0]), "+f"(oacc[2*vp][1]),
                      "+f"(oacc[2*vp][2]), "+f"(oacc[2*vp][3])
                    : "r"(a0), "r"(a1), "r"(a2), "r"(a3), "r"(r0), "r"(r1));
                asm volatile(
                    "mma.sync.aligned.m16n8k16.row.col.f32.f16.f16.f32 "
                    "{%0,%1,%2,%3}, {%4,%5,%6,%7}, {%8,%9}, {%0,%1,%2,%3};\n"
                    : "+f"(oacc[2*vp+1][0]), "+f"(oacc[2*vp+1][1]),
                      "+f"(oacc[2*vp+1][2]), "+f"(oacc[2*vp+1][3])
                    : "r"(a0), "r"(a1), "r"(a2), "r"(a3), "r"(r2), "r"(r3));
            }
        }

        __syncthreads();
        if (sc + 2 < 4) LOAD_KV(sc + 2, sc & 1);
    }

    float inv0 = 1.f / l0, inv1 = 1.f / l1;
    __half* orow0 = Om + (qrow0 + warp * 16 + g) * EMBEDN + KVN;
    __half* orow1 = orow0 + 8 * EMBEDN;
#pragma unroll
    for (int nb = 0; nb < 16; nb++) {
        int c = nb * 8 + 2 * tq;
        __half2 h0 = __floats2half2_rn(oacc[nb][0] * inv0, oacc[nb][1] * inv0);
        __half2 h1 = __floats2half2_rn(oacc[nb][2] * inv1, oacc[nb][3] * inv1);
        *reinterpret_cast<__half2*>(orow0 + c) = h0;
        *reinterpret_cast<__half2*>(orow1 + c) = h1;
    }
}

// ---------------- launch ----------------
extern "C" void kernel_launch(void* const* d_in, const int* in_sizes, int n_in,
                              void* d_out, int out_size)
{
    const float* key   = (const float*)d_in[0];
    const float* value = (const float*)d_in[1];
    const int*   elen  = (const int*)  d_in[2];
    const int*   y     = (const int*)  d_in[3];
    const float* E     = (const float*)d_in[4];
    const float* W1    = (const float*)d_in[5];
    const float* bi1   = (const float*)d_in[6];
    const float* bh1   = (const float*)d_in[7];
    const float* W2    = (const float*)d_in[8];
    const float* bi2   = (const float*)d_in[9];
    const float* bh2   = (const float*)d_in[10];
    const float* bout  = (const float*)d_in[11];
    float*       out   = (float*)d_out;

    float  *gates1, *gates2;
    __half *Eh, *W1h, *W2h, *keyh, *valueh, *h1h, *outctxh;
    cudaGetSymbolAddress((void**)&gates1, g_gates1);
    cudaGetSymbolAddress((void**)&gates2, g_gates2);
    cudaGetSymbolAddress((void**)&Eh,     g_Eh);
    cudaGetSymbolAddress((void**)&W1h,    g_W1h);
    cudaGetSymbolAddress((void**)&W2h,    g_W2h);
    cudaGetSymbolAddress((void**)&keyh,   g_keyh);
    cudaGetSymbolAddress((void**)&valueh, g_valueh);
    cudaGetSymbolAddress((void**)&h1h,    g_h1h);
    cudaGetSymbolAddress((void**)&outctxh,g_outctxh);

    cudaFuncSetAttribute(gemm_h<0>, cudaFuncAttributeMaxDynamicSharedMemorySize, GSMEM);
    cudaFuncSetAttribute(gemm_h<1>, cudaFuncAttributeMaxDynamicSharedMemorySize, GSMEM);
    cudaFuncSetAttribute(gemm_s,    cudaFuncAttributeMaxDynamicSharedMemorySize, S_SMEM);
    cudaFuncSetAttribute(logits_pa, cudaFuncAttributeMaxDynamicSharedMemorySize, PA_SMEM);
    cudaFuncSetAttribute(fattn,     cudaFuncAttributeMaxDynamicSharedMemorySize, FA_SMEM);

    // 0) all fp16 conversions in one launch
    conv_all<<<CONV_TOTAL / 256, 256>>>(
        (const float4*)E, (const float4*)W1, (const float4*)W2,
        (const float4*)key, (const float4*)value,
        (uint2*)Eh, (uint2*)W1h, (uint2*)W2h, (uint2*)keyh, (uint2*)valueh);

    // 1) gates1 = embed(tokens) @ W1'^T    (M=8192, N=1536, K=256)
    gemm_h<1><<<dim3(1536 / GBN, MROWS / GBM), 256, GSMEM>>>(
        Eh, W1h, gates1, EMBEDN, EMBEDN, EMBEDN, 3 * H1N, y);

    // 2) h1 = lstm_act(gates1) -> fp16
    {
        long total = (long)MROWS * H1N;
        act_lstm<<<(unsigned)((total + 255) / 256), 256>>>(
            gates1, bi1, bh1, h1h, H1N, H1N, total);
    }

    // 3) gates2 = h1 @ W2'^T   (M=8192, N=384, K=512), 384 CTAs
    gemm_s<<<dim3(384 / 128, MROWS / 64), 128, S_SMEM>>>(
        h1h, W2h, gates2, H1N, H1N, H1N, 3 * KVN);

    // 4) h2 = lstm_act(gates2) -> outctx[:, 0:128]
    {
        long total = (long)MROWS * KVN;
        act_lstm<<<(unsigned)((total + 255) / 256), 256>>>(
            gates2, bi2, bh2, outctxh, KVN, EMBEDN, total);
    }

    // 5) fused attention -> outctx[:, 128:256]
    fattn<<<dim3(TN / 64, BN_), 128, FA_SMEM>>>(
        outctxh, keyh, valueh, elen, outctxh);

    // 6) logits = E @ out_ctx^T + b_out -> out[b][v][t]  (PA_NT=16)
    logits_pa<<<dim3((MROWS / 128) / PA_NT, VOCABN / 128), 128, PA_SMEM>>>(
        Eh, outctxh, bout, out);

    (void)in_sizes; (void)n_in; (void)out_size;
}

// round 17
// speedup vs baseline: 1.0342x; 1.0057x over previous
#include <cuda_runtime.h>
#include <cuda_fp16.h>
#include <cstdint>

#define VOCABN 32000
#define EMBEDN 256
#define H1N    512
#define KVN    128
#define BN_    32
#define SN     512
#define TN     256
#define MROWS  (BN_*TN)   // 8192

// ---------------- scratch (static device globals; no allocation) ----------------
__device__ float  g_gates1[MROWS * 3 * H1N];
__device__ float  g_gates2[MROWS * 3 * KVN];
__device__ __half g_Eh  [VOCABN * EMBEDN];
__device__ __half g_W1h [3 * H1N * EMBEDN];
__device__ __half g_W2h [3 * KVN * H1N];
__device__ __half g_keyh[BN_ * SN * KVN];
__device__ __half g_valueh[BN_ * SN * KVN];
__device__ __half g_h1h [MROWS * H1N];
__device__ __half g_outctxh[MROWS * EMBEDN];

// ---------------- helpers ----------------
__device__ __forceinline__ void cp16(void* dst_smem, const void* src) {
    unsigned s = (unsigned)__cvta_generic_to_shared(dst_smem);
    asm volatile("cp.async.cg.shared.global [%0], [%1], 16;" :: "r"(s), "l"(src));
}
__device__ __forceinline__ float sigf(float x) { return 1.f / (1.f + expf(-x)); }

// ---------------- one-shot fp32->fp16 conversion for ALL operands ----------------
__global__ void conv_all(const float4* __restrict__ E,  const float4* __restrict__ W1,
                         const float4* __restrict__ W2, const float4* __restrict__ key,
                         const float4* __restrict__ value,
                         uint2* __restrict__ Eh,  uint2* __restrict__ W1h,
                         uint2* __restrict__ W2h, uint2* __restrict__ keyh,
                         uint2* __restrict__ valueh)
{
    const long nE   = (long)VOCABN * EMBEDN / 4;
    const long nW1g = H1N * EMBEDN / 4;
    const long nW2g = KVN * H1N / 4;
    const long nKey = (long)BN_ * SN * KVN / 4;

    long o = (long)blockIdx.x * blockDim.x + threadIdx.x;
    const float4* src; uint2* dst; long si, di;
    if (o < nE) { src = E; dst = Eh; si = o; di = o; }
    else {
        o -= nE;
        if (o < 3 * nW1g) {
            long gate = o >> 15, r = o & (nW1g - 1);
            long sg = (gate == 0) ? 0 : gate + 1;
            src = W1; dst = W1h; si = sg * nW1g + r; di = o;
        } else {
            o -= 3 * nW1g;
            if (o < 3 * nW2g) {
                long gate = o >> 14, r = o & (nW2g - 1);
                long sg = (gate == 0) ? 0 : gate + 1;
                src = W2; dst = W2h; si = sg * nW2g + r; di = o;
            } else {
                o -= 3 * nW2g;
                if (o < nKey) { src = key; dst = keyh; si = o; di = o; }
                else {
                    o -= nKey;
                    if (o >= nKey) return;
                    src = value; dst = valueh; si = o; di = o;
                }
            }
        }
    }
    float4 v = src[si];
    __half2 h0 = __floats2half2_rn(v.x, v.y);
    __half2 h1 = __floats2half2_rn(v.z, v.w);
    uint2 out;
    out.x = *reinterpret_cast<unsigned*>(&h0);
    out.y = *reinterpret_cast<unsigned*>(&h1);
    dst[di] = out;
}
#define CONV_TOTAL (2048000 + 3*32768 + 3*16384 + 524288 + 524288)

// =================================================================================
// PERSISTENT-A logits GEMM v3 (champion config, R13): 4 warps (2m x 2n), warp
// tile 64x64, 128 threads, 2 CTAs/SM. A resident XOR-swizzled; 3-slot B ring;
// single sync/chunk; .cs stores. PA_NT=8.
// =================================================================================
#define PA_NT  8
#define A_STR  256
#define A_SMH  (128 * A_STR)
#define B_STR  64
#define B_SLOT (128 * B_STR)
#define PA_SMEM ((A_SMH + 3 * B_SLOT) * 2)

__global__ void __launch_bounds__(128, 2)
logits_pa(const __half* __restrict__ Eh, const __half* __restrict__ Bm,
          const float* __restrict__ bias, float* __restrict__ out)
{
    extern __shared__ __half sh[];
    __half* Ash = sh;
    __half* Bsh = sh + A_SMH;

    const int tid  = threadIdx.x;
    const int warp = tid >> 5, lane = tid & 31;
    const int wm = warp >> 1, wn = warp & 1;
    const int g  = lane >> 2, tq = lane & 3;
    const int quad = lane >> 3, lr = lane & 7;
    const int bm0 = blockIdx.y * 128;
    const int nt0 = blockIdx.x * PA_NT;

#pragma unroll
    for (int i = 0; i < 32; i++) {
        int c = tid + i * 128;
        int r = c >> 5, seg = c & 31;
        int segw = (seg & ~7) | ((seg & 7) ^ (r & 7));
        cp16(&Ash[r * A_STR + segw * 8], Eh + (long)(bm0 + r) * EMBEDN + seg * 8);
    }
    asm volatile("cp.async.commit_group;" ::: "memory");

    int rB[8], sB[8], swB[8];
#pragma unroll
    for (int i = 0; i < 8; i++) {
        int c = tid + i * 128;
        rB[i] = c >> 3; sB[i] = c & 7;
        swB[i] = sB[i] ^ (rB[i] & 7);
    }
#pragma unroll
    for (int p = 0; p < 2; p++) {
        const __half* src = Bm + (long)(nt0 * 128) * EMBEDN + p * 64;
#pragma unroll
        for (int i = 0; i < 8; i++)
            cp16(&Bsh[p * B_SLOT + rB[i] * B_STR + swB[i] * 8],
                 src + (long)rB[i] * EMBEDN + sB[i] * 8);
        asm volatile("cp.async.commit_group;" ::: "memory");
    }

    float bb[8];
#pragma unroll
    for (int mi = 0; mi < 4; mi++)
#pragma unroll
        for (int rr = 0; rr < 2; rr++)
            bb[mi * 2 + rr] = bias[bm0 + wm * 64 + mi * 16 + g + rr * 8];

    float acc[4][8][4];
#pragma unroll
    for (int i = 0; i < 4; i++)
#pragma unroll
        for (int j = 0; j < 8; j++)
#pragma unroll
            for (int q = 0; q < 4; q++) acc[i][j][q] = 0.f;

    const int NCH = PA_NT * 4;
    int slot = 0;
    for (int gch = 0; gch < NCH; gch++) {
        if (gch == NCH - 1) {
            asm volatile("cp.async.wait_group 0;" ::: "memory");
        } else {
            asm volatile("cp.async.wait_group 1;" ::: "memory");
        }
        __syncthreads();

        if (gch + 2 < NCH) {
            int g2 = gch + 2;
            int nt = g2 >> 2, kc = g2 & 3;
            int s2 = g2 % 3;
            const __half* src = Bm + (long)((nt0 + nt) * 128) * EMBEDN + kc * 64;
#pragma unroll
            for (int i = 0; i < 8; i++)
                cp16(&Bsh[s2 * B_SLOT + rB[i] * B_STR + swB[i] * 8],
                     src + (long)rB[i] * EMBEDN + sB[i] * 8);
            asm volatile("cp.async.commit_group;" ::: "memory");
        }

        const __half* Bslot = Bsh + slot * B_SLOT;
        const int kbase = (gch & 3) * 64;

#pragma unroll
        for (int kk = 0; kk < 64; kk += 16) {
            unsigned af[4][4], bf[8][2];
#pragma unroll
            for (int mi = 0; mi < 4; mi++) {
                int row = wm * 64 + mi * 16 + lr + (quad & 1) * 8;
                int seg = ((kbase + kk) >> 3) + (quad >> 1);
                int segw = (seg & ~7) | ((seg & 7) ^ (row & 7));
                unsigned addr = (unsigned)__cvta_generic_to_shared(
                    &Ash[row * A_STR + segw * 8]);
                asm volatile(
                    "ldmatrix.sync.aligned.m8n8.x4.shared.b16 {%0,%1,%2,%3}, [%4];"
                    : "=r"(af[mi][0]), "=r"(af[mi][1]),
                      "=r"(af[mi][2]), "=r"(af[mi][3]) : "r"(addr));
            }
#pragma unroll
            for (int np = 0; np < 4; np++) {
                int row = wn * 64 + np * 16 + lr + (quad & 1) * 8;
                int seg = (kk >> 3) + (quad >> 1);
                int segw = seg ^ (row & 7);
                unsigned addr = (unsigned)__cvta_generic_to_shared(
                    &Bslot[row * B_STR + segw * 8]);
                unsigned r0, r1, r2, r3;
                asm volatile(
                    "ldmatrix.sync.aligned.m8n8.x4.shared.b16 {%0,%1,%2,%3}, [%4];"
                    : "=r"(r0), "=r"(r1), "=r"(r2), "=r"(r3) : "r"(addr));
                bf[2 * np + 0][0] = r0; bf[2 * np + 0][1] = r2;
                bf[2 * np + 1][0] = r1; bf[2 * np + 1][1] = r3;
            }
#pragma unroll
            for (int mi = 0; mi < 4; mi++)
#pragma unroll
                for (int ni = 0; ni < 8; ni++)
                    asm volatile(
                        "mma.sync.aligned.m16n8k16.row.col.f32.f16.f16.f32 "
                        "{%0,%1,%2,%3}, {%4,%5,%6,%7}, {%8,%9}, {%0,%1,%2,%3};\n"
                        : "+f"(acc[mi][ni][0]), "+f"(acc[mi][ni][1]),
                          "+f"(acc[mi][ni][2]), "+f"(acc[mi][ni][3])
                        : "r"(af[mi][0]), "r"(af[mi][1]),
                          "r"(af[mi][2]), "r"(af[mi][3]),
                          "r"(bf[ni][0]), "r"(bf[ni][1]));
        }
        slot = (slot + 1 == 3) ? 0 : slot + 1;

        if ((gch & 3) == 3) {
            int ncol0 = (nt0 + (gch >> 2)) * 128;
#pragma unroll
            for (int mi = 0; mi < 4; mi++) {
#pragma unroll
                for (int ni = 0; ni < 8; ni++) {
                    int row = bm0 + wm * 64 + mi * 16 + g;
                    int col = ncol0 + wn * 64 + ni * 8 + 2 * tq;
                    int bidx = col >> 8;
                    int t    = col & 255;
#pragma unroll
                    for (int rr = 0; rr < 2; rr++) {
                        int r = row + rr * 8;
                        float v0 = acc[mi][ni][rr * 2 + 0] + bb[mi * 2 + rr];
                        float v1 = acc[mi][ni][rr * 2 + 1] + bb[mi * 2 + rr];
                        __stcs(reinterpret_cast<float2*>(
                                   out + (long)bidx * VOCABN * TN + (long)r * TN + t),
                               make_float2(v0, v1));
                        acc[mi][ni][rr * 2 + 0] = 0.f;
                        acc[mi][ni][rr * 2 + 1] = 0.f;
                    }
                }
            }
        }
    }
}

// =================================================================================
// fp16 TN GEMM, CTA 128x128, BK=64, 3-stage cp.async (verified R7/R8/R13)
// MODE 0: plain | MODE 1: token-gather A
// =================================================================================
#define GBM 128
#define GBN 128
#define GBK 64
#define LDH 72
#define TSTG (128 * LDH)
#define STGH (2 * TSTG)
#define GSMEM (3 * STGH * 2)

template <int MODE>
__global__ void __launch_bounds__(256, 2)
gemm_h(const __half* __restrict__ A, const __half* __restrict__ Bmat,
       float* __restrict__ C,
       int K, int lda, int ldb, int ldc,
       const int* __restrict__ ytok)
{
    extern __shared__ __half sh[];

    const int tid  = threadIdx.x;
    const int warp = tid >> 5, lane = tid & 31;
    const int wm = warp >> 2, wn = warp & 3;
    const int g  = lane >> 2, tq = lane & 3;
    const int quad = lane >> 3, lr = lane & 7;
    const int bm0 = blockIdx.y * GBM;
    const int bn0 = blockIdx.x * GBN;

    int rA[4], sA_[4];
    const __half* srcA[4];
    const __half* srcB[4];
#pragma unroll
    for (int i = 0; i < 4; i++) {
        int c   = tid + i * 256;
        int r   = c >> 3;
        int seg = c & 7;
        rA[i] = r; sA_[i] = seg;
        if (MODE == 1) {
            int m   = bm0 + r;
            int tok = ((m & (TN - 1)) == 0) ? 0 : ytok[m - 1];
            srcA[i] = A + (long)tok * lda + seg * 8;
        } else {
            srcA[i] = A + (long)(bm0 + r) * lda + seg * 8;
        }
        srcB[i] = Bmat + (long)(bn0 + r) * ldb + seg * 8;
    }

    float acc[4][4][4];
#pragma unroll
    for (int i = 0; i < 4; i++)
#pragma unroll
        for (int j = 0; j < 4; j++)
#pragma unroll
            for (int q = 0; q < 4; q++) acc[i][j][q] = 0.f;

    const int nt = K / GBK;

#pragma unroll
    for (int s = 0; s < 2; s++) {
        if (s < nt) {
            __half* Ad = sh + s * STGH;
            __half* Bd = Ad + TSTG;
            int k0 = s * GBK;
#pragma unroll
            for (int i = 0; i < 4; i++) {
                cp16(&Ad[rA[i] * LDH + sA_[i] * 8], srcA[i] + k0);
                cp16(&Bd[rA[i] * LDH + sA_[i] * 8], srcB[i] + k0);
            }
            asm volatile("cp.async.commit_group;" ::: "memory");
        }
    }

    int buf = 0;
    for (int kt = 0; kt < nt; kt++) {
        if (kt + 1 < nt) {
            asm volatile("cp.async.wait_group 1;" ::: "memory");
        } else {
            asm volatile("cp.async.wait_group 0;" ::: "memory");
        }
        __syncthreads();

        if (kt + 2 < nt) {
            int sb2 = (kt + 2) % 3;
            __half* Ad = sh + sb2 * STGH;
            __half* Bd = Ad + TSTG;
            int k0 = (kt + 2) * GBK;
#pragma unroll
            for (int i = 0; i < 4; i++) {
                cp16(&Ad[rA[i] * LDH + sA_[i] * 8], srcA[i] + k0);
                cp16(&Bd[rA[i] * LDH + sA_[i] * 8], srcB[i] + k0);
            }
            asm volatile("cp.async.commit_group;" ::: "memory");
        }

        const __half* Asb = sh + buf * STGH;
        const __half* Bsb = Asb + TSTG;

#pragma unroll
        for (int kk = 0; kk < GBK; kk += 16) {
            unsigned af[4][4], bf[4][2];
#pragma unroll
            for (int mi = 0; mi < 4; mi++) {
                int row = wm * 64 + mi * 16 + lr + (quad & 1) * 8;
                int col = kk + (quad >> 1) * 8;
                unsigned addr = (unsigned)__cvta_generic_to_shared(
                    &Asb[row * LDH + col]);
                asm volatile(
                    "ldmatrix.sync.aligned.m8n8.x4.shared.b16 {%0,%1,%2,%3}, [%4];"
                    : "=r"(af[mi][0]), "=r"(af[mi][1]),
                      "=r"(af[mi][2]), "=r"(af[mi][3]) : "r"(addr));
            }
#pragma unroll
            for (int np = 0; np < 2; np++) {
                int row = wn * 32 + np * 16 + lr + (quad & 1) * 8;
                int col = kk + (quad >> 1) * 8;
                unsigned addr = (unsigned)__cvta_generic_to_shared(
                    &Bsb[row * LDH + col]);
                unsigned r0, r1, r2, r3;
                asm volatile(
                    "ldmatrix.sync.aligned.m8n8.x4.shared.b16 {%0,%1,%2,%3}, [%4];"
                    : "=r"(r0), "=r"(r1), "=r"(r2), "=r"(r3) : "r"(addr));
                bf[2 * np + 0][0] = r0; bf[2 * np + 0][1] = r2;
                bf[2 * np + 1][0] = r1; bf[2 * np + 1][1] = r3;
            }
#pragma unroll
            for (int mi = 0; mi < 4; mi++)
#pragma unroll
                for (int ni = 0; ni < 4; ni++)
                    asm volatile(
                        "mma.sync.aligned.m16n8k16.row.col.f32.f16.f16.f32 "
                        "{%0,%1,%2,%3}, {%4,%5,%6,%7}, {%8,%9}, {%0,%1,%2,%3};\n"
                        : "+f"(acc[mi][ni][0]), "+f"(acc[mi][ni][1]),
                          "+f"(acc[mi][ni][2]), "+f"(acc[mi][ni][3])
                        : "r"(af[mi][0]), "r"(af[mi][1]),
                          "r"(af[mi][2]), "r"(af[mi][3]),
                          "r"(bf[ni][0]), "r"(bf[ni][1]));
        }
        buf = (buf + 1) % 3;
        __syncthreads();
    }

#pragma unroll
    for (int mi = 0; mi < 4; mi++) {
#pragma unroll
        for (int ni = 0; ni < 4; ni++) {
            int row = bm0 + wm * 64 + mi * 16 + g;
            int col = bn0 + wn * 32 + ni * 8 + 2 * tq;
#pragma unroll
            for (int rr = 0; rr < 2; rr++) {
                int r = row + rr * 8;
                *reinterpret_cast<float2*>(C + (long)r * ldc + col) =
                    make_float2(acc[mi][ni][rr * 2 + 0], acc[mi][ni][rr * 2 + 1]);
            }
        }
    }
}

// =================================================================================
// SMALL-M fp16 TN GEMM for gates2 (verified R12/R13): CTA 64x128, 128 threads.
// =================================================================================
#define S_ASTG (64 * LDH)
#define S_BSTG (128 * LDH)
#define S_STG  (S_ASTG + S_BSTG)
#define S_SMEM (3 * S_STG * 2)

__global__ void __launch_bounds__(128, 2)
gemm_s(const __half* __restrict__ A, const __half* __restrict__ Bmat,
       float* __restrict__ C, int K, int lda, int ldb, int ldc)
{
    extern __shared__ __half sh[];

    const int tid  = threadIdx.x;
    const int warp = tid >> 5, lane = tid & 31;
    const int wn = warp;
    const int g  = lane >> 2, tq = lane & 3;
    const int quad = lane >> 3, lr = lane & 7;
    const int bm0 = blockIdx.y * 64;
    const int bn0 = blockIdx.x * 128;

    int rA[4], sA_[4];
    const __half* srcA[4];
#pragma unroll
    for (int i = 0; i < 4; i++) {
        int c = tid + i * 128;
        rA[i] = c >> 3; sA_[i] = c & 7;
        srcA[i] = A + (long)(bm0 + rA[i]) * lda + sA_[i] * 8;
    }
    int rBs[8], sBs[8];
    const __half* srcB[8];
#pragma unroll
    for (int i = 0; i < 8; i++) {
        int c = tid + i * 128;
        rBs[i] = c >> 3; sBs[i] = c & 7;
        srcB[i] = Bmat + (long)(bn0 + rBs[i]) * ldb + sBs[i] * 8;
    }

    float acc[4][4][4];
#pragma unroll
    for (int i = 0; i < 4; i++)
#pragma unroll
        for (int j = 0; j < 4; j++)
#pragma unroll
            for (int q = 0; q < 4; q++) acc[i][j][q] = 0.f;

    const int nt = K / GBK;

#pragma unroll
    for (int s = 0; s < 2; s++) {
        __half* Ad = sh + s * S_STG;
        __half* Bd = Ad + S_ASTG;
        int k0 = s * GBK;
#pragma unroll
        for (int i = 0; i < 4; i++)
            cp16(&Ad[rA[i] * LDH + sA_[i] * 8], srcA[i] + k0);
#pragma unroll
        for (int i = 0; i < 8; i++)
            cp16(&Bd[rBs[i] * LDH + sBs[i] * 8], srcB[i] + k0);
        asm volatile("cp.async.commit_group;" ::: "memory");
    }

    int buf = 0;
    for (int kt = 0; kt < nt; kt++) {
        if (kt + 1 < nt) {
            asm volatile("cp.async.wait_group 1;" ::: "memory");
        } else {
            asm volatile("cp.async.wait_group 0;" ::: "memory");
        }
        __syncthreads();

        if (kt + 2 < nt) {
            int sb2 = (kt + 2) % 3;
            __half* Ad = sh + sb2 * S_STG;
            __half* Bd = Ad + S_ASTG;
            int k0 = (kt + 2) * GBK;
#pragma unroll
            for (int i = 0; i < 4; i++)
                cp16(&Ad[rA[i] * LDH + sA_[i] * 8], srcA[i] + k0);
#pragma unroll
            for (int i = 0; i < 8; i++)
                cp16(&Bd[rBs[i] * LDH + sBs[i] * 8], srcB[i] + k0);
            asm volatile("cp.async.commit_group;" ::: "memory");
        }

        const __half* Asb = sh + buf * S_STG;
        const __half* Bsb = Asb + S_ASTG;

#pragma unroll
        for (int kk = 0; kk < GBK; kk += 16) {
            unsigned af[4][4], bf[4][2];
#pragma unroll
            for (int mi = 0; mi < 4; mi++) {
                int row = mi * 16 + lr + (quad & 1) * 8;
                int col = kk + (quad >> 1) * 8;
                unsigned addr = (unsigned)__cvta_generic_to_shared(
                    &Asb[row * LDH + col]);
                asm volatile(
                    "ldmatrix.sync.aligned.m8n8.x4.shared.b16 {%0,%1,%2,%3}, [%4];"
                    : "=r"(af[mi][0]), "=r"(af[mi][1]),
                      "=r"(af[mi][2]), "=r"(af[mi][3]) : "r"(addr));
            }
#pragma unroll
            for (int np = 0; np < 2; np++) {
                int row = wn * 32 + np * 16 + lr + (quad & 1) * 8;
                int col = kk + (quad >> 1) * 8;
                unsigned addr = (unsigned)__cvta_generic_to_shared(
                    &Bsb[row * LDH + col]);
                unsigned r0, r1, r2, r3;
                asm volatile(
                    "ldmatrix.sync.aligned.m8n8.x4.shared.b16 {%0,%1,%2,%3}, [%4];"
                    : "=r"(r0), "=r"(r1), "=r"(r2), "=r"(r3) : "r"(addr));
                bf[2 * np + 0][0] = r0; bf[2 * np + 0][1] = r2;
                bf[2 * np + 1][0] = r1; bf[2 * np + 1][1] = r3;
            }
#pragma unroll
            for (int mi = 0; mi < 4; mi++)
#pragma unroll
                for (int ni = 0; ni < 4; ni++)
                    asm volatile(
                        "mma.sync.aligned.m16n8k16.row.col.f32.f16.f16.f32 "
                        "{%0,%1,%2,%3}, {%4,%5,%6,%7}, {%8,%9}, {%0,%1,%2,%3};\n"
                        : "+f"(acc[mi][ni][0]), "+f"(acc[mi][ni][1]),
                          "+f"(acc[mi][ni][2]), "+f"(acc[mi][ni][3])
                        : "r"(af[mi][0]), "r"(af[mi][1]),
                          "r"(af[mi][2]), "r"(af[mi][3]),
                          "r"(bf[ni][0]), "r"(bf[ni][1]));
        }
        buf = (buf + 1) % 3;
        __syncthreads();
    }

#pragma unroll
    for (int mi = 0; mi < 4; mi++) {
#pragma unroll
        for (int ni = 0; ni < 4; ni++) {
            int row = bm0 + mi * 16 + g;
            int col = bn0 + wn * 32 + ni * 8 + 2 * tq;
#pragma unroll
            for (int rr = 0; rr < 2; rr++) {
                int r = row + rr * 8;
                *reinterpret_cast<float2*>(C + (long)r * ldc + col) =
                    make_float2(acc[mi][ni][rr * 2 + 0], acc[mi][ni][rr * 2 + 1]);
            }
        }
    }
}

// ---------------- LSTM activation: gates packed [i | g | o] (3H), fp16 out ------
__global__ void act_lstm(const float* __restrict__ gates,
                         const float* __restrict__ b_ih,
                         const float* __restrict__ b_hh,
                         __half* __restrict__ h, int H, int ldout, long total)
{
    long idx = (long)blockIdx.x * blockDim.x + threadIdx.x;
    if (idx >= total) return;
    int  j = (int)(idx & (H - 1));
    long m = idx / H;
    const float* gr = gates + m * 3 * H;
    float iv = gr[j]         + b_ih[j]         + b_hh[j];
    float gv = gr[H + j]     + b_ih[2 * H + j] + b_hh[2 * H + j];
    float ov = gr[2 * H + j] + b_ih[3 * H + j] + b_hh[3 * H + j];
    float c  = sigf(iv) * tanhf(gv);
    h[m * ldout + j] = __float2half_rn(sigf(ov) * tanhf(c));
}

// =================================================================================
// Fused flash attention (verified R9/R11/R13)
// =================================================================================
#define FA_LD  136
#define FA_QSZ (64 * FA_LD)
#define FA_KSZ (128 * FA_LD)
#define FA_SMEM ((FA_QSZ + 4 * FA_KSZ) * 2)

#define LOAD_KV(sc_, bufi_) do { \
    const __half* ks_ = Km + ((long)b * SN + (sc_) * 128) * KVN; \
    const __half* vs_ = Vm + ((long)b * SN + (sc_) * 128) * KVN; \
    __half* kd_ = Ks + (bufi_) * FA_KSZ; \
    __half* vd_ = Vs + (bufi_) * FA_KSZ; \
    _Pragma("unroll") \
    for (int i_ = 0; i_ < 16; i_++) { \
        int c_ = tid + i_ * 128; \
        int r_ = c_ >> 4, sg_ = c_ & 15; \
        cp16(&kd_[r_ * FA_LD + sg_ * 8], ks_ + r_ * KVN + sg_ * 8); \
        cp16(&vd_[r_ * FA_LD + sg_ * 8], vs_ + r_ * KVN + sg_ * 8); \
    } \
    asm volatile("cp.async.commit_group;" ::: "memory"); \
} while (0)

__global__ void __launch_bounds__(128, 1)
fattn(const __half* __restrict__ Qm,
      const __half* __restrict__ Km,
      const __half* __restrict__ Vm,
      const int* __restrict__ enc_len,
      __half* __restrict__ Om)
{
    extern __shared__ __half sm[];
    __half* Qs = sm;
    __half* Ks = sm + FA_QSZ;
    __half* Vs = Ks + 2 * FA_KSZ;

    const int tid = threadIdx.x;
    const int warp = tid >> 5, lane = tid & 31;
    const int g = lane >> 2, tq = lane & 3;
    const int quad = lane >> 3, lr = lane & 7;
    const int b  = blockIdx.y;
    const int t0 = blockIdx.x * 64;
    const long qrow0 = (long)b * TN + t0;
    const int len = enc_len[b];

#pragma unroll
    for (int i = 0; i < 8; i++) {
        int c = tid + i * 128;
        int r = c >> 4, seg = c & 15;
        cp16(&Qs[r * FA_LD + seg * 8], Qm + (qrow0 + r) * EMBEDN + seg * 8);
    }
    asm volatile("cp.async.commit_group;" ::: "memory");

    LOAD_KV(0, 0);
    LOAD_KV(1, 1);
    asm volatile("cp.async.wait_group 1;" ::: "memory");
    __syncthreads();

    unsigned qf[8][4];
#pragma unroll
    for (int kb = 0; kb < 8; kb++) {
        int row = warp * 16 + lr + (quad & 1) * 8;
        int col = kb * 16 + (quad >> 1) * 8;
        unsigned addr = (unsigned)__cvta_generic_to_shared(&Qs[row * FA_LD + col]);
        asm volatile(
            "ldmatrix.sync.aligned.m8n8.x4.shared.b16 {%0,%1,%2,%3}, [%4];"
            : "=r"(qf[kb][0]), "=r"(qf[kb][1]), "=r"(qf[kb][2]), "=r"(qf[kb][3])
            : "r"(addr));
    }

    float oacc[16][4];
#pragma unroll
    for (int i = 0; i < 16; i++)
#pragma unroll
        for (int q = 0; q < 4; q++) oacc[i][q] = 0.f;
    float m0 = -1e30f, m1 = -1e30f, l0 = 0.f, l1 = 0.f;

    for (int sc = 0; sc < 4; sc++) {
        if (sc == 1 || sc == 2) {
            asm volatile("cp.async.wait_group 1;" ::: "memory");
            __syncthreads();
        } else if (sc == 3) {
            asm volatile("cp.async.wait_group 0;" ::: "memory");
            __syncthreads();
        }
        const __half* Kb = Ks + (sc & 1) * FA_KSZ;
        const __half* Vb = Vs + (sc & 1) * FA_KSZ;

        float eacc[16][4];
#pragma unroll
        for (int i = 0; i < 16; i++)
#pragma unroll
            for (int q = 0; q < 4; q++) eacc[i][q] = 0.f;

#pragma unroll
        for (int kb = 0; kb < 8; kb++) {
#pragma unroll
            for (int np = 0; np < 8; np++) {
                int row = np * 16 + lr + (quad & 1) * 8;
                int col = kb * 16 + (quad >> 1) * 8;
                unsigned addr = (unsigned)__cvta_generic_to_shared(
                    &Kb[row * FA_LD + col]);
                unsigned r0, r1, r2, r3;
                asm volatile(
                    "ldmatrix.sync.aligned.m8n8.x4.shared.b16 {%0,%1,%2,%3}, [%4];"
                    : "=r"(r0), "=r"(r1), "=r"(r2), "=r"(r3) : "r"(addr));
                asm volatile(
                    "mma.sync.aligned.m16n8k16.row.col.f32.f16.f16.f32 "
                    "{%0,%1,%2,%3}, {%4,%5,%6,%7}, {%8,%9}, {%0,%1,%2,%3};\n"
                    : "+f"(eacc[2*np][0]), "+f"(eacc[2*np][1]),
                      "+f"(eacc[2*np][2]), "+f"(eacc[2*np][3])
                    : "r"(qf[kb][0]), "r"(qf[kb][1]), "r"(qf[kb][2]), "r"(qf[kb][3]),
                      "r"(r0), "r"(r2));
                asm volatile(
                    "mma.sync.aligned.m16n8k16.row.col.f32.f16.f16.f32 "
                    "{%0,%1,%2,%3}, {%4,%5,%6,%7}, {%8,%9}, {%0,%1,%2,%3};\n"
                    : "+f"(eacc[2*np+1][0]), "+f"(eacc[2*np+1][1]),
                      "+f"(eacc[2*np+1][2]), "+f"(eacc[2*np+1][3])
                    : "r"(qf[kb][0]), "r"(qf[kb][1]), "r"(qf[kb][2]), "r"(qf[kb][3]),
                      "r"(r1), "r"(r3));
            }
        }

        float mx0 = -1e30f, mx1 = -1e30f;
#pragma unroll
        for (int nb = 0; nb < 16; nb++) {
            int c0 = sc * 128 + nb * 8 + 2 * tq;
            if (c0 >= len)     { eacc[nb][0] = -1e9f; eacc[nb][2] = -1e9f; }
            if (c0 + 1 >= len) { eacc[nb][1] = -1e9f; eacc[nb][3] = -1e9f; }
            mx0 = fmaxf(mx0, fmaxf(eacc[nb][0], eacc[nb][1]));
            mx1 = fmaxf(mx1, fmaxf(eacc[nb][2], eacc[nb][3]));
        }
        mx0 = fmaxf(mx0, __shfl_xor_sync(0xffffffffu, mx0, 1));
        mx0 = fmaxf(mx0, __shfl_xor_sync(0xffffffffu, mx0, 2));
        mx1 = fmaxf(mx1, __shfl_xor_sync(0xffffffffu, mx1, 1));
        mx1 = fmaxf(mx1, __shfl_xor_sync(0xffffffffu, mx1, 2));

        float mn0 = fmaxf(m0, mx0), mn1 = fmaxf(m1, mx1);
        float cf0 = __expf(m0 - mn0), cf1 = __expf(m1 - mn1);
        m0 = mn0; m1 = mn1;
        l0 *= cf0; l1 *= cf1;
#pragma unroll
        for (int nb = 0; nb < 16; nb++) {
            oacc[nb][0] *= cf0; oacc[nb][1] *= cf0;
            oacc[nb][2] *= cf1; oacc[nb][3] *= cf1;
        }

        unsigned pf[16][2];
        float s0 = 0.f, s1 = 0.f;
#pragma unroll
        for (int nb = 0; nb < 16; nb++) {
            float p0 = __expf(eacc[nb][0] - m0);
            float p1 = __expf(eacc[nb][1] - m0);
            float p2 = __expf(eacc[nb][2] - m1);
            float p3 = __expf(eacc[nb][3] - m1);
            s0 += p0 + p1; s1 += p2 + p3;
            __half2 h01 = __floats2half2_rn(p0, p1);
            __half2 h23 = __floats2half2_rn(p2, p3);
            pf[nb][0] = *reinterpret_cast<unsigned*>(&h01);
            pf[nb][1] = *reinterpret_cast<unsigned*>(&h23);
        }
        s0 += __shfl_xor_sync(0xffffffffu, s0, 1);
        s0 += __shfl_xor_sync(0xffffffffu, s0, 2);
        s1 += __shfl_xor_sync(0xffffffffu, s1, 1);
        s1 += __shfl_xor_sync(0xffffffffu, s1, 2);
        l0 += s0; l1 += s1;

#pragma unroll
        for (int kb2 = 0; kb2 < 8; kb2++) {
            unsigned a0 = pf[2*kb2][0], a1 = pf[2*kb2][1];
            unsigned a2 = pf[2*kb2+1][0], a3 = pf[2*kb2+1][1];
#pragma unroll
            for (int vp = 0; vp < 8; vp++) {
                int row = kb2 * 16 + lr + (quad & 1) * 8;
                int col = vp * 16 + (quad >> 1) * 8;
                unsigned addr = (unsigned)__cvta_generic_to_shared(
                    &Vb[row * FA_LD + col]);
                unsigned r0, r1, r2, r3;
                asm volatile(
                    "ldmatrix.sync.aligned.m8n8.x4.trans.shared.b16 {%0,%1,%2,%3}, [%4];"
                    : "=r"(r0), "=r"(r1), "=r"(r2), "=r"(r3) : "r"(addr));
                asm volatile(
                    "mma.sync.aligned.m16n8k16.row.col.f32.f16.f16.f32 "
                    "{%0,%1,%2,%3}, {%4,%5,%6,%7}, {%8,%9}, {%0,%1,%2,%3};\n"
                    : "+f"(oacc[2*vp][0]), "+f"(oacc[2*vp][1]),
                      "+f"(oacc[2*vp][2]), "+f"(oacc[2*vp][3])
                    : "r"(a0), "r"(a1), "r"(a2), "r"(a3), "r"(r0), "r"(r1));
                asm volatile(
                    "mma.sync.aligned.m16n8k16.row.col.f32.f16.f16.f32 "
                    "{%0,%1,%2,%3}, {%4,%5,%6,%7}, {%8,%9}, {%0,%1,%2,%3};\n"
                    : "+f"(oacc[2*vp+1][0]), "+f"(oacc[2*vp+1][1]),
                      "+f"(oacc[2*vp+1][2]), "+f"(oacc[2*vp+1][3])
                    : "r"(a0), "r"(a1), "r"(a2), "r"(a3), "r"(r2), "r"(r3));
            }
        }

        __syncthreads();
        if (sc + 2 < 4) LOAD_KV(sc + 2, sc & 1);
    }

    float inv0 = 1.f / l0, inv1 = 1.f / l1;
    __half* orow0 = Om + (qrow0 + warp * 16 + g) * EMBEDN + KVN;
    __half* orow1 = orow0 + 8 * EMBEDN;
#pragma unroll
    for (int nb = 0; nb < 16; nb++) {
        int c = nb * 8 + 2 * tq;
        __half2 h0 = __floats2half2_rn(oacc[nb][0] * inv0, oacc[nb][1] * inv0);
        __half2 h1 = __floats2half2_rn(oacc[nb][2] * inv1, oacc[nb][3] * inv1);
        *reinterpret_cast<__half2*>(orow0 + c) = h0;
        *reinterpret_cast<__half2*>(orow1 + c) = h1;
    }
}

// ---------------- launch ----------------
extern "C" void kernel_launch(void* const* d_in, const int* in_sizes, int n_in,
                              void* d_out, int out_size)
{
    const float* key   = (const float*)d_in[0];
    const float* value = (const float*)d_in[1];
    const int*   elen  = (const int*)  d_in[2];
    const int*   y     = (const int*)  d_in[3];
    const float* E     = (const float*)d_in[4];
    const float* W1    = (const float*)d_in[5];
    const float* bi1   = (const float*)d_in[6];
    const float* bh1   = (const float*)d_in[7];
    const float* W2    = (const float*)d_in[8];
    const float* bi2   = (const float*)d_in[9];
    const float* bh2   = (const float*)d_in[10];
    const float* bout  = (const float*)d_in[11];
    float*       out   = (float*)d_out;

    float  *gates1, *gates2;
    __half *Eh, *W1h, *W2h, *keyh, *valueh, *h1h, *outctxh;
    cudaGetSymbolAddress((void**)&gates1, g_gates1);
    cudaGetSymbolAddress((void**)&gates2, g_gates2);
    cudaGetSymbolAddress((void**)&Eh,     g_Eh);
    cudaGetSymbolAddress((void**)&W1h,    g_W1h);
    cudaGetSymbolAddress((void**)&W2h,    g_W2h);
    cudaGetSymbolAddress((void**)&keyh,   g_keyh);
    cudaGetSymbolAddress((void**)&valueh, g_valueh);
    cudaGetSymbolAddress((void**)&h1h,    g_h1h);
    cudaGetSymbolAddress((void**)&outctxh,g_outctxh);

    cudaFuncSetAttribute(gemm_h<0>, cudaFuncAttributeMaxDynamicSharedMemorySize, GSMEM);
    cudaFuncSetAttribute(gemm_h<1>, cudaFuncAttributeMaxDynamicSharedMemorySize, GSMEM);
    cudaFuncSetAttribute(gemm_s,    cudaFuncAttributeMaxDynamicSharedMemorySize, S_SMEM);
    cudaFuncSetAttribute(logits_pa, cudaFuncAttributeMaxDynamicSharedMemorySize, PA_SMEM);
    cudaFuncSetAttribute(fattn,     cudaFuncAttributeMaxDynamicSharedMemorySize, FA_SMEM);

    // 0) all fp16 conversions in one launch
    conv_all<<<CONV_TOTAL / 256, 256>>>(
        (const float4*)E, (const float4*)W1, (const float4*)W2,
        (const float4*)key, (const float4*)value,
        (uint2*)Eh, (uint2*)W1h, (uint2*)W2h, (uint2*)keyh, (uint2*)valueh);

    // 1) gates1 = embed(tokens) @ W1'^T    (M=8192, N=1536, K=256)
    gemm_h<1><<<dim3(1536 / GBN, MROWS / GBM), 256, GSMEM>>>(
        Eh, W1h, gates1, EMBEDN, EMBEDN, EMBEDN, 3 * H1N, y);

    // 2) h1 = lstm_act(gates1) -> fp16
    {
        long total = (long)MROWS * H1N;
        act_lstm<<<(unsigned)((total + 255) / 256), 256>>>(
            gates1, bi1, bh1, h1h, H1N, H1N, total);
    }

    // 3) gates2 = h1 @ W2'^T   (M=8192, N=384, K=512), 384 CTAs
    gemm_s<<<dim3(384 / 128, MROWS / 64), 128, S_SMEM>>>(
        h1h, W2h, gates2, H1N, H1N, H1N, 3 * KVN);

    // 4) h2 = lstm_act(gates2) -> outctx[:, 0:128]
    {
        long total = (long)MROWS * KVN;
        act_lstm<<<(unsigned)((total + 255) / 256), 256>>>(
            gates2, bi2, bh2, outctxh, KVN, EMBEDN, total);
    }

    // 5) fused attention -> outctx[:, 128:256]
    fattn<<<dim3(TN / 64, BN_), 128, FA_SMEM>>>(
        outctxh, keyh, valueh, elen, outctxh);

    // 6) logits = E @ out_ctx^T + b_out -> out[b][v][t]  (PA_NT=8, champion)
    logits_pa<<<dim3((MROWS / 128) / PA_NT, VOCABN / 128), 128, PA_SMEM>>>(
        Eh, outctxh, bout, out);

    (void)in_sizes; (void)n_in; (void)out_size;
}